// round 1
// baseline (speedup 1.0000x reference)
#include <cuda_runtime.h>

#define BATCH 128
#define NH    8
#define NT    256
#define HDIM  64
#define MODEL 512
#define NBH   (BATCH*NH)    // 1024
#define MTOT  (BATCH*NT)    // 32768

// Scratch (static __device__ — no runtime allocation)
__device__ float g_q[(size_t)NBH*NT*HDIM];
__device__ float g_k[(size_t)NBH*NT*HDIM];
__device__ float g_v[(size_t)NBH*NT*HDIM];
__device__ float g_S[(size_t)NBH*NT*NT];
__device__ float g_P[(size_t)NBH*NT*NT];
__device__ float g_oh[(size_t)MTOT*MODEL];

// ---------------------------------------------------------------------------
// Kernel 1: QKV = x @ qkv_w^T + qkv_b, scattered into q (scaled), k, v
// C[32768, 1536], K = 512.  64x64 tile, 4x4 per thread.
// ---------------------------------------------------------------------------
__global__ __launch_bounds__(256) void qkv_kernel(
    const float* __restrict__ x, const float* __restrict__ w,
    const float* __restrict__ bias)
{
    __shared__ float As[16][64];
    __shared__ float Bs[16][64];
    const int m0 = blockIdx.y * 64;
    const int n0 = blockIdx.x * 64;
    const int tid = threadIdx.x;
    const int tm = (tid >> 4) << 2;
    const int tn = (tid & 15) << 2;
    const int lr = tid >> 2;
    const int lc = (tid & 3) << 2;
    float acc[4][4] = {};
    for (int k0 = 0; k0 < MODEL; k0 += 16) {
        float4 a4 = *(const float4*)(x + (size_t)(m0 + lr) * MODEL + k0 + lc);
        float4 b4 = *(const float4*)(w + (size_t)(n0 + lr) * MODEL + k0 + lc);
        As[lc+0][lr]=a4.x; As[lc+1][lr]=a4.y; As[lc+2][lr]=a4.z; As[lc+3][lr]=a4.w;
        Bs[lc+0][lr]=b4.x; Bs[lc+1][lr]=b4.y; Bs[lc+2][lr]=b4.z; Bs[lc+3][lr]=b4.w;
        __syncthreads();
        #pragma unroll
        for (int kk = 0; kk < 16; kk++) {
            float4 av = *(const float4*)&As[kk][tm];
            float4 bv = *(const float4*)&Bs[kk][tn];
            float a[4] = {av.x, av.y, av.z, av.w};
            float b[4] = {bv.x, bv.y, bv.z, bv.w};
            #pragma unroll
            for (int i = 0; i < 4; i++)
                #pragma unroll
                for (int j = 0; j < 4; j++)
                    acc[i][j] = fmaf(a[i], b[j], acc[i][j]);
        }
        __syncthreads();
    }
    #pragma unroll
    for (int i = 0; i < 4; i++) {
        const int row = m0 + tm + i;
        const int bi = row >> 8, nt = row & 255;
        #pragma unroll
        for (int j = 0; j < 4; j++) {
            const int col = n0 + tn + j;
            float c = acc[i][j] + bias[col];
            const int s = col >> 9;
            const int h = (col >> 6) & 7;
            const int d = col & 63;
            const size_t off = (((size_t)(bi * NH + h) * NT) + nt) * HDIM + d;
            if (s == 0)      g_q[off] = c * 0.125f;   // scale = 64^-0.5
            else if (s == 1) g_k[off] = c;
            else             g_v[off] = c;
        }
    }
}

// ---------------------------------------------------------------------------
// Kernel 2: S[bh] = q[bh] @ k[bh]^T   (256x256, K=64)
// grid: (16 tiles of 64x64, 1024 bh)
// ---------------------------------------------------------------------------
__global__ __launch_bounds__(256) void s_kernel()
{
    __shared__ float As[16][64];
    __shared__ float Bs[16][64];
    const int bh = blockIdx.y;
    const int m0 = (blockIdx.x >> 2) * 64;
    const int n0 = (blockIdx.x & 3) * 64;
    const float* q = g_q + (size_t)bh * NT * HDIM;
    const float* k = g_k + (size_t)bh * NT * HDIM;
    const int tid = threadIdx.x;
    const int tm = (tid >> 4) << 2;
    const int tn = (tid & 15) << 2;
    const int lr = tid >> 2;
    const int lc = (tid & 3) << 2;
    float acc[4][4] = {};
    for (int k0 = 0; k0 < HDIM; k0 += 16) {
        float4 a4 = *(const float4*)(q + (m0 + lr) * HDIM + k0 + lc);
        float4 b4 = *(const float4*)(k + (n0 + lr) * HDIM + k0 + lc);
        As[lc+0][lr]=a4.x; As[lc+1][lr]=a4.y; As[lc+2][lr]=a4.z; As[lc+3][lr]=a4.w;
        Bs[lc+0][lr]=b4.x; Bs[lc+1][lr]=b4.y; Bs[lc+2][lr]=b4.z; Bs[lc+3][lr]=b4.w;
        __syncthreads();
        #pragma unroll
        for (int kk = 0; kk < 16; kk++) {
            float4 av = *(const float4*)&As[kk][tm];
            float4 bv = *(const float4*)&Bs[kk][tn];
            float a[4] = {av.x, av.y, av.z, av.w};
            float b[4] = {bv.x, bv.y, bv.z, bv.w};
            #pragma unroll
            for (int i = 0; i < 4; i++)
                #pragma unroll
                for (int j = 0; j < 4; j++)
                    acc[i][j] = fmaf(a[i], b[j], acc[i][j]);
        }
        __syncthreads();
    }
    float* Sp = g_S + (size_t)bh * NT * NT;
    #pragma unroll
    for (int i = 0; i < 4; i++)
        #pragma unroll
        for (int j = 0; j < 4; j++)
            Sp[(m0 + tm + i) * NT + n0 + tn + j] = acc[i][j];
}

// ---------------------------------------------------------------------------
// Kernel 3: P = softmax(S + depthwise_conv15x1(S) + pe_b + rpb_bias)
// grid: (16 row-chunks of 16, 1024 bh), 256 threads (8 warps, 2 rows/warp)
// ---------------------------------------------------------------------------
__global__ __launch_bounds__(256) void conv_softmax_kernel(
    const float* __restrict__ pe_w, const float* __restrict__ pe_b,
    const float* __restrict__ rpb)
{
    __shared__ float sr[30][NT];   // rows i0-7 .. i0+22 (zero-padded)
    const int bh = blockIdx.y;
    const int h  = bh & 7;
    const int i0 = blockIdx.x * 16;
    const float* S = g_S + (size_t)bh * NT * NT;
    float*       P = g_P + (size_t)bh * NT * NT;
    const int tid = threadIdx.x;
    #pragma unroll
    for (int r = 0; r < 30; r++) {
        const int g = i0 - 7 + r;
        sr[r][tid] = (g >= 0 && g < NT) ? S[g * NT + tid] : 0.f;
    }
    __syncthreads();
    float w[15];
    #pragma unroll
    for (int t = 0; t < 15; t++) w[t] = pe_w[h * 15 + t];
    const float pb = pe_b[h];
    const int warp = tid >> 5, lane = tid & 31;
    #pragma unroll
    for (int rr = 0; rr < 2; rr++) {
        const int li = warp * 2 + rr;          // 0..15
        const int ii = i0 + li;
        const int ri = ii >> 4, ci = ii & 15;
        float vals[8];
        #pragma unroll
        for (int e = 0; e < 8; e++) {
            const int j = lane + e * 32;
            float conv = 0.f;
            #pragma unroll
            for (int t = 0; t < 15; t++)
                conv = fmaf(sr[li + t][j], w[t], conv);
            const int rj = j >> 4, cj = j & 15;
            const int idx = (ri - rj + 15) * 31 + (ci - cj + 15);
            vals[e] = sr[li + 7][j] + conv + pb + __ldg(&rpb[idx * 8 + h]);
        }
        float mx = vals[0];
        #pragma unroll
        for (int e = 1; e < 8; e++) mx = fmaxf(mx, vals[e]);
        #pragma unroll
        for (int o = 16; o; o >>= 1) mx = fmaxf(mx, __shfl_xor_sync(0xffffffffu, mx, o));
        float sum = 0.f;
        #pragma unroll
        for (int e = 0; e < 8; e++) { vals[e] = expf(vals[e] - mx); sum += vals[e]; }
        #pragma unroll
        for (int o = 16; o; o >>= 1) sum += __shfl_xor_sync(0xffffffffu, sum, o);
        const float inv = 1.f / sum;
        #pragma unroll
        for (int e = 0; e < 8; e++)
            P[ii * NT + lane + e * 32] = vals[e] * inv;
    }
}

// ---------------------------------------------------------------------------
// Kernel 4: O[bh] = P[bh] @ V[bh]   (256x64, K=256) -> g_oh (B, N, H*HD)
// grid: (4 M-tiles of 64, 1024 bh)
// ---------------------------------------------------------------------------
__global__ __launch_bounds__(256) void av_kernel()
{
    __shared__ float As[16][64];
    __shared__ float Bs[16][64];
    const int bh = blockIdx.y;
    const int m0 = blockIdx.x * 64;
    const float* P = g_P + (size_t)bh * NT * NT;
    const float* V = g_v + (size_t)bh * NT * HDIM;
    const int tid = threadIdx.x;
    const int tm = (tid >> 4) << 2;
    const int tn = (tid & 15) << 2;
    const int lr = tid >> 2;
    const int lc = (tid & 3) << 2;
    const int br = tid >> 4;
    const int bc = (tid & 15) << 2;
    float acc[4][4] = {};
    for (int k0 = 0; k0 < NT; k0 += 16) {
        float4 a4 = *(const float4*)(P + (m0 + lr) * NT + k0 + lc);
        As[lc+0][lr]=a4.x; As[lc+1][lr]=a4.y; As[lc+2][lr]=a4.z; As[lc+3][lr]=a4.w;
        float4 b4 = *(const float4*)(V + (k0 + br) * HDIM + bc);
        *(float4*)&Bs[br][bc] = b4;
        __syncthreads();
        #pragma unroll
        for (int kk = 0; kk < 16; kk++) {
            float4 av = *(const float4*)&As[kk][tm];
            float4 bv = *(const float4*)&Bs[kk][tn];
            float a[4] = {av.x, av.y, av.z, av.w};
            float b[4] = {bv.x, bv.y, bv.z, bv.w};
            #pragma unroll
            for (int i = 0; i < 4; i++)
                #pragma unroll
                for (int j = 0; j < 4; j++)
                    acc[i][j] = fmaf(a[i], b[j], acc[i][j]);
        }
        __syncthreads();
    }
    const int bi = bh >> 3, hh = bh & 7;
    #pragma unroll
    for (int i = 0; i < 4; i++) {
        const int itok = m0 + tm + i;
        #pragma unroll
        for (int j = 0; j < 4; j++) {
            const int d = tn + j;
            g_oh[((size_t)(bi * NT + itok)) * MODEL + hh * HDIM + d] = acc[i][j];
        }
    }
}

// ---------------------------------------------------------------------------
// Kernel 5: out = g_oh @ proj_w^T + proj_b   (32768x512, K=512)
// ---------------------------------------------------------------------------
__global__ __launch_bounds__(256) void proj_kernel(
    const float* __restrict__ w, const float* __restrict__ bias,
    float* __restrict__ out)
{
    __shared__ float As[16][64];
    __shared__ float Bs[16][64];
    const int m0 = blockIdx.y * 64;
    const int n0 = blockIdx.x * 64;
    const int tid = threadIdx.x;
    const int tm = (tid >> 4) << 2;
    const int tn = (tid & 15) << 2;
    const int lr = tid >> 2;
    const int lc = (tid & 3) << 2;
    float acc[4][4] = {};
    for (int k0 = 0; k0 < MODEL; k0 += 16) {
        float4 a4 = *(const float4*)(g_oh + (size_t)(m0 + lr) * MODEL + k0 + lc);
        float4 b4 = *(const float4*)(w + (size_t)(n0 + lr) * MODEL + k0 + lc);
        As[lc+0][lr]=a4.x; As[lc+1][lr]=a4.y; As[lc+2][lr]=a4.z; As[lc+3][lr]=a4.w;
        Bs[lc+0][lr]=b4.x; Bs[lc+1][lr]=b4.y; Bs[lc+2][lr]=b4.z; Bs[lc+3][lr]=b4.w;
        __syncthreads();
        #pragma unroll
        for (int kk = 0; kk < 16; kk++) {
            float4 av = *(const float4*)&As[kk][tm];
            float4 bv = *(const float4*)&Bs[kk][tn];
            float a[4] = {av.x, av.y, av.z, av.w};
            float b[4] = {bv.x, bv.y, bv.z, bv.w};
            #pragma unroll
            for (int i = 0; i < 4; i++)
                #pragma unroll
                for (int j = 0; j < 4; j++)
                    acc[i][j] = fmaf(a[i], b[j], acc[i][j]);
        }
        __syncthreads();
    }
    #pragma unroll
    for (int i = 0; i < 4; i++) {
        const int row = m0 + tm + i;
        #pragma unroll
        for (int j = 0; j < 4; j++) {
            const int col = n0 + tn + j;
            out[(size_t)row * MODEL + col] = acc[i][j] + bias[col];
        }
    }
}

// ---------------------------------------------------------------------------
extern "C" void kernel_launch(void* const* d_in, const int* in_sizes, int n_in,
                              void* d_out, int out_size)
{
    (void)in_sizes; (void)n_in; (void)out_size;
    const float* x      = (const float*)d_in[0];
    const float* qkv_w  = (const float*)d_in[1];
    const float* qkv_b  = (const float*)d_in[2];
    const float* pe_w   = (const float*)d_in[3];
    const float* pe_b   = (const float*)d_in[4];
    const float* rpb    = (const float*)d_in[5];
    const float* proj_w = (const float*)d_in[6];
    const float* proj_b = (const float*)d_in[7];
    float* out = (float*)d_out;

    qkv_kernel<<<dim3(24, 512), 256>>>(x, qkv_w, qkv_b);
    s_kernel<<<dim3(16, 1024), 256>>>();
    conv_softmax_kernel<<<dim3(16, 1024), 256>>>(pe_w, pe_b, rpb);
    av_kernel<<<dim3(4, 1024), 256>>>();
    proj_kernel<<<dim3(8, 512), 256>>>(proj_w, proj_b, out);
}

// round 3
// speedup vs baseline: 1.0990x; 1.0990x over previous
#include <cuda_runtime.h>
#include <cuda_bf16.h>
#include <cstdint>

#define BATCH 128
#define NH    8
#define NT    256
#define HDIM  64
#define MODEL 512
#define NBH   (BATCH*NH)    // 1024
#define MTOT  (BATCH*NT)    // 32768
#define QKVN  (3*NH*HDIM)   // 1536
#define KX    1536          // extended K = 3*512

// ---------------- scratch (static __device__, no runtime allocation) -------
__device__ float g_q[(size_t)NBH*NT*HDIM];
__device__ float g_k[(size_t)NBH*NT*HDIM];
__device__ float g_v[(size_t)NBH*NT*HDIM];
__device__ float g_S[(size_t)NBH*NT*NT];
__device__ float g_P[(size_t)NBH*NT*NT];
__device__ __nv_bfloat16 g_xs[(size_t)MTOT*KX];    // [Ah|Al|Ah] of x
__device__ __nv_bfloat16 g_qws[(size_t)QKVN*KX];   // [Bh|Bh|Bl] of qkv_w
__device__ __nv_bfloat16 g_pws[(size_t)MODEL*KX];  // [Bh|Bh|Bl] of proj_w
__device__ __nv_bfloat16 g_ohs[(size_t)MTOT*KX];   // [Ah|Al|Ah] of attn out

// ---------------- helpers ---------------------------------------------------
__device__ __forceinline__ uint32_t smem_u32(const void* p) {
    uint32_t a;
    asm("{ .reg .u64 t; cvta.to.shared.u64 t, %1; cvt.u32.u64 %0, t; }"
        : "=r"(a) : "l"(p));
    return a;
}
__device__ __forceinline__ void cp16(uint32_t s, const void* g) {
    asm volatile("cp.async.cg.shared.global [%0], [%1], 16;" :: "r"(s), "l"(g));
}
#define CP_COMMIT() asm volatile("cp.async.commit_group;")
#define CP_WAIT2()  asm volatile("cp.async.wait_group 2;")
__device__ __forceinline__ void ldm4(uint32_t& r0, uint32_t& r1, uint32_t& r2,
                                     uint32_t& r3, uint32_t a) {
    asm volatile("ldmatrix.sync.aligned.m8n8.x4.shared.b16 {%0,%1,%2,%3}, [%4];"
                 : "=r"(r0), "=r"(r1), "=r"(r2), "=r"(r3) : "r"(a));
}
__device__ __forceinline__ void mma16816(float* c, const uint32_t* a,
                                         uint32_t b0, uint32_t b1) {
    asm volatile(
        "mma.sync.aligned.m16n8k16.row.col.f32.bf16.bf16.f32 "
        "{%0,%1,%2,%3}, {%4,%5,%6,%7}, {%8,%9}, {%0,%1,%2,%3};"
        : "+f"(c[0]), "+f"(c[1]), "+f"(c[2]), "+f"(c[3])
        : "r"(a[0]), "r"(a[1]), "r"(a[2]), "r"(a[3]), "r"(b0), "r"(b1));
}
__device__ __forceinline__ void split1(float v, __nv_bfloat16& h, __nv_bfloat16& l) {
    h = __float2bfloat16(v);
    l = __float2bfloat16(v - __bfloat162float(h));
}

// ---------------- split kernels ---------------------------------------------
// A-style: [Ah | Al | Ah]   (rows R, src K=512)
__global__ void split_a_kernel(const float* __restrict__ s, __nv_bfloat16* d,
                               int total) {
    int i = blockIdx.x * 256 + threadIdx.x;
    if (i >= total) return;
    int r = i >> 9, k = i & 511;
    __nv_bfloat16 h, l;
    split1(s[i], h, l);
    size_t base = (size_t)r * KX + k;
    d[base] = h; d[base + 512] = l; d[base + 1024] = h;
}
// B-style: [Bh | Bh | Bl]
__global__ void split_b_kernel(const float* __restrict__ s, __nv_bfloat16* d,
                               int total) {
    int i = blockIdx.x * 256 + threadIdx.x;
    if (i >= total) return;
    int r = i >> 9, k = i & 511;
    __nv_bfloat16 h, l;
    split1(s[i], h, l);
    size_t base = (size_t)r * KX + k;
    d[base] = h; d[base + 512] = h; d[base + 1024] = l;
}

// ---------------- bf16 mma.sync GEMM ---------------------------------------
// C[M,N] = A[M,KX] @ B[N,KX]^T (+bias).  BM=128 BN=128 BK=32, 4 stages.
// MODE 0: qkv (scatter into q*0.125 / k / v).  MODE 1: proj -> out.
#define BM 128
#define BN 128
#define BK 32
#define NSTG 4
#define ROWB 80u                       // padded row: 40 bf16 = 80B
#define STGB (2u * BM * ROWB)          // A tile + B tile = 20480B
#define GSMEM (NSTG * STGB)            // 81920B

template<int MODE>
__global__ __launch_bounds__(256, 1) void gemm_mma(
    const __nv_bfloat16* __restrict__ gA, const __nv_bfloat16* __restrict__ gB,
    const float* __restrict__ bias, float* __restrict__ outp)
{
    extern __shared__ char smem[];
    const uint32_t sb = smem_u32(smem);
    const int tid = threadIdx.x, wid = tid >> 5, lane = tid & 31;
    const int m0 = blockIdx.y * BM;
    const int n0 = blockIdx.x * BN;

    const int warp_m = (wid & 3) * 32;
    const int warp_n = (wid >> 2) * 64;

    // cp.async chunk mapping: 512 A-chunks + 512 B-chunks of 16B per stage
    const int c0r = tid >> 2, c0c = (tid & 3) * 8;          // chunk row/col(e)
    const int c1r = (tid + 256) >> 2, c1c = ((tid + 256) & 3) * 8;

    auto load_stage = [&](int ks, int buf) {
        const size_t kofs = (size_t)ks * BK;
        const uint32_t abase = sb + buf * STGB;
        const uint32_t bbase = abase + BM * ROWB;
        cp16(abase + c0r * ROWB + c0c * 2, gA + (size_t)(m0 + c0r) * KX + kofs + c0c);
        cp16(abase + c1r * ROWB + c1c * 2, gA + (size_t)(m0 + c1r) * KX + kofs + c1c);
        cp16(bbase + c0r * ROWB + c0c * 2, gB + (size_t)(n0 + c0r) * KX + kofs + c0c);
        cp16(bbase + c1r * ROWB + c1c * 2, gB + (size_t)(n0 + c1r) * KX + kofs + c1c);
    };

    const int NK = KX / BK;   // 48
    load_stage(0, 0); CP_COMMIT();
    load_stage(1, 1); CP_COMMIT();
    load_stage(2, 2); CP_COMMIT();

    float acc[2][8][4] = {};

    // ldmatrix source addresses (element offsets within a stage)
    const int a_row = warp_m + (lane & 15);
    const int a_col = (lane >> 4) * 8;
    const int b_row = warp_n + (lane & 7) + ((lane >> 4) << 3);
    const int b_col = ((lane >> 3) & 1) * 8;

    for (int ks = 0; ks < NK; ks++) {
        CP_WAIT2();
        __syncthreads();
        const int buf = ks & (NSTG - 1);
        const uint32_t abase = sb + buf * STGB;
        const uint32_t bbase = abase + BM * ROWB;
        #pragma unroll
        for (int kk = 0; kk < 2; kk++) {
            uint32_t af[2][4], bf[4][4];
            #pragma unroll
            for (int im = 0; im < 2; im++)
                ldm4(af[im][0], af[im][1], af[im][2], af[im][3],
                     abase + (a_row + im * 16) * ROWB + (kk * 16 + a_col) * 2);
            #pragma unroll
            for (int jn = 0; jn < 4; jn++)
                ldm4(bf[jn][0], bf[jn][1], bf[jn][2], bf[jn][3],
                     bbase + (b_row + jn * 16) * ROWB + (kk * 16 + b_col) * 2);
            #pragma unroll
            for (int im = 0; im < 2; im++)
                #pragma unroll
                for (int jn = 0; jn < 4; jn++) {
                    mma16816(acc[im][jn * 2 + 0], af[im], bf[jn][0], bf[jn][1]);
                    mma16816(acc[im][jn * 2 + 1], af[im], bf[jn][2], bf[jn][3]);
                }
        }
        __syncthreads();
        if (ks + NSTG - 1 < NK)
            load_stage(ks + NSTG - 1, (ks + NSTG - 1) & (NSTG - 1));
        CP_COMMIT();
    }

    // ---------------- epilogue ----------------
    const int mb = m0 + warp_m + (lane >> 2);
    #pragma unroll
    for (int im = 0; im < 2; im++) {
        #pragma unroll
        for (int j = 0; j < 8; j++) {
            const int col = n0 + warp_n + j * 8 + (lane & 3) * 2;
            #pragma unroll
            for (int half = 0; half < 2; half++) {
                const int m = mb + im * 16 + half * 8;
                float v0 = acc[im][j][half * 2 + 0] + bias[col];
                float v1 = acc[im][j][half * 2 + 1] + bias[col + 1];
                if (MODE == 0) {
                    const int sct = col >> 9, h = (col >> 6) & 7, d = col & 63;
                    float* dst = (sct == 0) ? g_q : (sct == 1) ? g_k : g_v;
                    if (sct == 0) { v0 *= 0.125f; v1 *= 0.125f; }
                    const int bi = m >> 8, nt = m & 255;
                    float2* dp = (float2*)(dst +
                        (((size_t)(bi * NH + h) * NT + nt) * HDIM + d));
                    *dp = make_float2(v0, v1);
                } else {
                    *(float2*)(outp + (size_t)m * MODEL + col) = make_float2(v0, v1);
                }
            }
        }
    }
}

// ---------------- Kernel: S[bh] = q @ k^T  (256x256, K=64) -----------------
__global__ __launch_bounds__(256) void s_kernel()
{
    __shared__ float As[16][64];
    __shared__ float Bs[16][64];
    const int bh = blockIdx.y;
    const int m0 = (blockIdx.x >> 2) * 64;
    const int n0 = (blockIdx.x & 3) * 64;
    const float* q = g_q + (size_t)bh * NT * HDIM;
    const float* k = g_k + (size_t)bh * NT * HDIM;
    const int tid = threadIdx.x;
    const int tm = (tid >> 4) << 2;
    const int tn = (tid & 15) << 2;
    const int lr = tid >> 2;
    const int lc = (tid & 3) << 2;
    float acc[4][4] = {};
    for (int k0 = 0; k0 < HDIM; k0 += 16) {
        float4 a4 = *(const float4*)(q + (m0 + lr) * HDIM + k0 + lc);
        float4 b4 = *(const float4*)(k + (n0 + lr) * HDIM + k0 + lc);
        As[lc+0][lr]=a4.x; As[lc+1][lr]=a4.y; As[lc+2][lr]=a4.z; As[lc+3][lr]=a4.w;
        Bs[lc+0][lr]=b4.x; Bs[lc+1][lr]=b4.y; Bs[lc+2][lr]=b4.z; Bs[lc+3][lr]=b4.w;
        __syncthreads();
        #pragma unroll
        for (int kk = 0; kk < 16; kk++) {
            float4 av = *(const float4*)&As[kk][tm];
            float4 bv = *(const float4*)&Bs[kk][tn];
            float a[4] = {av.x, av.y, av.z, av.w};
            float b[4] = {bv.x, bv.y, bv.z, bv.w};
            #pragma unroll
            for (int i = 0; i < 4; i++)
                #pragma unroll
                for (int j = 0; j < 4; j++)
                    acc[i][j] = fmaf(a[i], b[j], acc[i][j]);
        }
        __syncthreads();
    }
    float* Sp = g_S + (size_t)bh * NT * NT;
    #pragma unroll
    for (int i = 0; i < 4; i++)
        #pragma unroll
        for (int j = 0; j < 4; j++)
            Sp[(m0 + tm + i) * NT + n0 + tn + j] = acc[i][j];
}

// ---------------- Kernel: conv + bias + softmax -----------------------------
__global__ __launch_bounds__(256) void conv_softmax_kernel(
    const float* __restrict__ pe_w, const float* __restrict__ pe_b,
    const float* __restrict__ rpb)
{
    __shared__ float sr[30][NT];
    const int bh = blockIdx.y;
    const int h  = bh & 7;
    const int i0 = blockIdx.x * 16;
    const float* S = g_S + (size_t)bh * NT * NT;
    float*       P = g_P + (size_t)bh * NT * NT;
    const int tid = threadIdx.x;
    #pragma unroll
    for (int r = 0; r < 30; r++) {
        const int g = i0 - 7 + r;
        sr[r][tid] = (g >= 0 && g < NT) ? S[g * NT + tid] : 0.f;
    }
    __syncthreads();
    float w[15];
    #pragma unroll
    for (int t = 0; t < 15; t++) w[t] = pe_w[h * 15 + t];
    const float pb = pe_b[h];
    const int warp = tid >> 5, lane = tid & 31;
    #pragma unroll
    for (int rr = 0; rr < 2; rr++) {
        const int li = warp * 2 + rr;
        const int ii = i0 + li;
        const int ri = ii >> 4, ci = ii & 15;
        float vals[8];
        #pragma unroll
        for (int e = 0; e < 8; e++) {
            const int j = lane + e * 32;
            float conv = 0.f;
            #pragma unroll
            for (int t = 0; t < 15; t++)
                conv = fmaf(sr[li + t][j], w[t], conv);
            const int rj = j >> 4, cj = j & 15;
            const int idx = (ri - rj + 15) * 31 + (ci - cj + 15);
            vals[e] = sr[li + 7][j] + conv + pb + __ldg(&rpb[idx * 8 + h]);
        }
        float mx = vals[0];
        #pragma unroll
        for (int e = 1; e < 8; e++) mx = fmaxf(mx, vals[e]);
        #pragma unroll
        for (int o = 16; o; o >>= 1) mx = fmaxf(mx, __shfl_xor_sync(0xffffffffu, mx, o));
        float sum = 0.f;
        #pragma unroll
        for (int e = 0; e < 8; e++) { vals[e] = expf(vals[e] - mx); sum += vals[e]; }
        #pragma unroll
        for (int o = 16; o; o >>= 1) sum += __shfl_xor_sync(0xffffffffu, sum, o);
        const float inv = 1.f / sum;
        #pragma unroll
        for (int e = 0; e < 8; e++)
            P[ii * NT + lane + e * 32] = vals[e] * inv;
    }
}

// ---------------- Kernel: O = P @ V, write split into g_ohs -----------------
__global__ __launch_bounds__(256) void av_kernel()
{
    __shared__ float As[16][64];
    __shared__ float Bs[16][64];
    const int bh = blockIdx.y;
    const int m0 = blockIdx.x * 64;
    const float* P = g_P + (size_t)bh * NT * NT;
    const float* V = g_v + (size_t)bh * NT * HDIM;
    const int tid = threadIdx.x;
    const int tm = (tid >> 4) << 2;
    const int tn = (tid & 15) << 2;
    const int lr = tid >> 2;
    const int lc = (tid & 3) << 2;
    const int br = tid >> 4;
    const int bc = (tid & 15) << 2;
    float acc[4][4] = {};
    for (int k0 = 0; k0 < NT; k0 += 16) {
        float4 a4 = *(const float4*)(P + (m0 + lr) * NT + k0 + lc);
        As[lc+0][lr]=a4.x; As[lc+1][lr]=a4.y; As[lc+2][lr]=a4.z; As[lc+3][lr]=a4.w;
        float4 b4 = *(const float4*)(V + (k0 + br) * HDIM + bc);
        *(float4*)&Bs[br][bc] = b4;
        __syncthreads();
        #pragma unroll
        for (int kk = 0; kk < 16; kk++) {
            float4 av = *(const float4*)&As[kk][tm];
            float4 bv = *(const float4*)&Bs[kk][tn];
            float a[4] = {av.x, av.y, av.z, av.w};
            float b[4] = {bv.x, bv.y, bv.z, bv.w};
            #pragma unroll
            for (int i = 0; i < 4; i++)
                #pragma unroll
                for (int j = 0; j < 4; j++)
                    acc[i][j] = fmaf(a[i], b[j], acc[i][j]);
        }
        __syncthreads();
    }
    const int bi = bh >> 3, hh = bh & 7;
    #pragma unroll
    for (int i = 0; i < 4; i++) {
        const int itok = m0 + tm + i;
        #pragma unroll
        for (int j = 0; j < 4; j++) {
            const size_t base = (size_t)(bi * NT + itok) * KX + hh * HDIM + tn + j;
            __nv_bfloat16 hi, lo;
            split1(acc[i][j], hi, lo);
            g_ohs[base] = hi;
            g_ohs[base + 512] = lo;
            g_ohs[base + 1024] = hi;
        }
    }
}

// ---------------------------------------------------------------------------
extern "C" void kernel_launch(void* const* d_in, const int* in_sizes, int n_in,
                              void* d_out, int out_size)
{
    (void)in_sizes; (void)n_in; (void)out_size;
    const float* x      = (const float*)d_in[0];
    const float* qkv_w  = (const float*)d_in[1];
    const float* qkv_b  = (const float*)d_in[2];
    const float* pe_w   = (const float*)d_in[3];
    const float* pe_b   = (const float*)d_in[4];
    const float* rpb    = (const float*)d_in[5];
    const float* proj_w = (const float*)d_in[6];
    const float* proj_b = (const float*)d_in[7];
    float* out = (float*)d_out;

    static bool attr_done = false;
    if (!attr_done) {
        cudaFuncSetAttribute(gemm_mma<0>, cudaFuncAttributeMaxDynamicSharedMemorySize, GSMEM);
        cudaFuncSetAttribute(gemm_mma<1>, cudaFuncAttributeMaxDynamicSharedMemorySize, GSMEM);
        attr_done = true;
    }

    __nv_bfloat16 *xs, *qws, *pws, *ohs;
    cudaGetSymbolAddress((void**)&xs,  g_xs);
    cudaGetSymbolAddress((void**)&qws, g_qws);
    cudaGetSymbolAddress((void**)&pws, g_pws);
    cudaGetSymbolAddress((void**)&ohs, g_ohs);

    split_a_kernel<<<(MTOT * MODEL + 255) / 256, 256>>>(x, xs, MTOT * MODEL);
    split_b_kernel<<<(QKVN * MODEL + 255) / 256, 256>>>(qkv_w, qws, QKVN * MODEL);
    split_b_kernel<<<(MODEL * MODEL + 255) / 256, 256>>>(proj_w, pws, MODEL * MODEL);

    gemm_mma<0><<<dim3(QKVN / BN, MTOT / BM), 256, GSMEM>>>(xs, qws, qkv_b, nullptr);

    s_kernel<<<dim3(16, NBH), 256>>>();
    conv_softmax_kernel<<<dim3(16, NBH), 256>>>(pe_w, pe_b, rpb);
    av_kernel<<<dim3(4, NBH), 256>>>();

    gemm_mma<1><<<dim3(MODEL / BN, MTOT / BM), 256, GSMEM>>>(ohs, pws, proj_b, out);
}

// round 5
// speedup vs baseline: 1.2127x; 1.1035x over previous
#include <cuda_runtime.h>
#include <cuda_bf16.h>
#include <cstdint>

#define BATCH 128
#define NH    8
#define NT    256
#define HDIM  64
#define MODEL 512
#define NBH   (BATCH*NH)    // 1024
#define MTOT  (BATCH*NT)    // 32768
#define QKVN  (3*NH*HDIM)   // 1536
#define KX    1536          // extended K = 3*512

// ---------------- scratch (static __device__, no runtime allocation) -------
__device__ float g_q[(size_t)NBH*NT*HDIM];
__device__ float g_k[(size_t)NBH*NT*HDIM];
__device__ float g_v[(size_t)NBH*NT*HDIM];
__device__ float g_S[(size_t)NBH*NT*NT];
__device__ float g_P[(size_t)NBH*NT*NT];
__device__ __nv_bfloat16 g_xs[(size_t)MTOT*KX];    // [Ah|Al|Ah] of x
__device__ __nv_bfloat16 g_qws[(size_t)QKVN*KX];   // [Bh|Bh|Bl] of qkv_w
__device__ __nv_bfloat16 g_pws[(size_t)MODEL*KX];  // [Bh|Bh|Bl] of proj_w
__device__ __nv_bfloat16 g_ohs[(size_t)MTOT*KX];   // [Ah|Al|Ah] of attn out

// ---------------- helpers ---------------------------------------------------
__device__ __forceinline__ uint32_t smem_u32(const void* p) {
    uint32_t a;
    asm("{ .reg .u64 t; cvta.to.shared.u64 t, %1; cvt.u32.u64 %0, t; }"
        : "=r"(a) : "l"(p));
    return a;
}
__device__ __forceinline__ void cp16(uint32_t s, const void* g) {
    asm volatile("cp.async.cg.shared.global [%0], [%1], 16;" :: "r"(s), "l"(g));
}
#define CP_COMMIT() asm volatile("cp.async.commit_group;")
#define CP_WAIT1()  asm volatile("cp.async.wait_group 1;")
__device__ __forceinline__ void ldm4(uint32_t& r0, uint32_t& r1, uint32_t& r2,
                                     uint32_t& r3, uint32_t a) {
    asm volatile("ldmatrix.sync.aligned.m8n8.x4.shared.b16 {%0,%1,%2,%3}, [%4];"
                 : "=r"(r0), "=r"(r1), "=r"(r2), "=r"(r3) : "r"(a));
}
__device__ __forceinline__ void mma16816(float* c, const uint32_t* a,
                                         uint32_t b0, uint32_t b1) {
    asm volatile(
        "mma.sync.aligned.m16n8k16.row.col.f32.bf16.bf16.f32 "
        "{%0,%1,%2,%3}, {%4,%5,%6,%7}, {%8,%9}, {%0,%1,%2,%3};"
        : "+f"(c[0]), "+f"(c[1]), "+f"(c[2]), "+f"(c[3])
        : "r"(a[0]), "r"(a[1]), "r"(a[2]), "r"(a[3]), "r"(b0), "r"(b1));
}
__device__ __forceinline__ void split1(float v, __nv_bfloat16& h, __nv_bfloat16& l) {
    h = __float2bfloat16(v);
    l = __float2bfloat16(v - __bfloat162float(h));
}

// ---------------- split kernels ---------------------------------------------
// A-style: [Ah | Al | Ah]   (rows R, src K=512)
__global__ void split_a_kernel(const float* __restrict__ s, __nv_bfloat16* d,
                               int total) {
    int i = blockIdx.x * 256 + threadIdx.x;
    if (i >= total) return;
    int r = i >> 9, k = i & 511;
    __nv_bfloat16 h, l;
    split1(s[i], h, l);
    size_t base = (size_t)r * KX + k;
    d[base] = h; d[base + 512] = l; d[base + 1024] = h;
}
// B-style: [Bh | Bh | Bl]
__global__ void split_b_kernel(const float* __restrict__ s, __nv_bfloat16* d,
                               int total) {
    int i = blockIdx.x * 256 + threadIdx.x;
    if (i >= total) return;
    int r = i >> 9, k = i & 511;
    __nv_bfloat16 h, l;
    split1(s[i], h, l);
    size_t base = (size_t)r * KX + k;
    d[base] = h; d[base + 512] = h; d[base + 1024] = l;
}

// ---------------- bf16 mma.sync GEMM ---------------------------------------
// C[M,N] = A[M,KX] @ B[N,KX]^T (+bias).  BM=128 BN=128 BK=32, 3 stages.
// MODE 0: qkv (scatter into q*0.125 / k / v).  MODE 1: proj -> out.
#define BM 128
#define BN 128
#define BK 32
#define NSTG 3
#define ROWB 80u                       // padded row: 40 bf16 = 80B
#define STGB (2u * BM * ROWB)          // A tile + B tile = 20480B
#define GSMEM (NSTG * STGB)            // 61440B

template<int MODE>
__global__ __launch_bounds__(256, 2) void gemm_mma(
    const __nv_bfloat16* __restrict__ gA, const __nv_bfloat16* __restrict__ gB,
    const float* __restrict__ bias, float* __restrict__ outp)
{
    extern __shared__ char smem[];
    const uint32_t sb = smem_u32(smem);
    const int tid = threadIdx.x, wid = tid >> 5, lane = tid & 31;
    const int m0 = blockIdx.y * BM;
    const int n0 = blockIdx.x * BN;

    const int warp_m = (wid & 3) * 32;
    const int warp_n = (wid >> 2) * 64;

    // cp.async chunk mapping: 512 A-chunks + 512 B-chunks of 16B per stage
    const int c0r = tid >> 2, c0c = (tid & 3) * 8;          // chunk row/col(e)
    const int c1r = (tid + 256) >> 2, c1c = ((tid + 256) & 3) * 8;

    auto load_stage = [&](int ks, int buf) {
        const size_t kofs = (size_t)ks * BK;
        const uint32_t abase = sb + buf * STGB;
        const uint32_t bbase = abase + BM * ROWB;
        cp16(abase + c0r * ROWB + c0c * 2, gA + (size_t)(m0 + c0r) * KX + kofs + c0c);
        cp16(abase + c1r * ROWB + c1c * 2, gA + (size_t)(m0 + c1r) * KX + kofs + c1c);
        cp16(bbase + c0r * ROWB + c0c * 2, gB + (size_t)(n0 + c0r) * KX + kofs + c0c);
        cp16(bbase + c1r * ROWB + c1c * 2, gB + (size_t)(n0 + c1r) * KX + kofs + c1c);
    };

    const int NK = KX / BK;   // 48
    load_stage(0, 0); CP_COMMIT();
    load_stage(1, 1); CP_COMMIT();

    float acc[2][8][4] = {};

    // ldmatrix source addresses (element offsets within a stage)
    const int a_row = warp_m + (lane & 15);
    const int a_col = (lane >> 4) * 8;
    const int b_row = warp_n + (lane & 7) + ((lane >> 4) << 3);
    const int b_col = ((lane >> 3) & 1) * 8;

    for (int ks = 0; ks < NK; ks++) {
        CP_WAIT1();                 // stage ks resident
        __syncthreads();            // also orders prev-iter reads of dst buf
        // prefetch stage ks+2 into buf (ks+2)%3 (consumed at iter ks-1)
        const int pf = ks + NSTG - 1;
        if (pf < NK) {
            int pb = pf % NSTG;
            load_stage(pf, pb);
        }
        CP_COMMIT();
        const int buf = ks % NSTG;
        const uint32_t abase = sb + buf * STGB;
        const uint32_t bbase = abase + BM * ROWB;
        #pragma unroll
        for (int kk = 0; kk < 2; kk++) {
            uint32_t af[2][4];
            #pragma unroll
            for (int im = 0; im < 2; im++)
                ldm4(af[im][0], af[im][1], af[im][2], af[im][3],
                     abase + (a_row + im * 16) * ROWB + (kk * 16 + a_col) * 2);
            #pragma unroll
            for (int jn = 0; jn < 4; jn++) {
                uint32_t b0, b1, b2, b3;
                ldm4(b0, b1, b2, b3,
                     bbase + (b_row + jn * 16) * ROWB + (kk * 16 + b_col) * 2);
                #pragma unroll
                for (int im = 0; im < 2; im++) {
                    mma16816(acc[im][jn * 2 + 0], af[im], b0, b1);
                    mma16816(acc[im][jn * 2 + 1], af[im], b2, b3);
                }
            }
        }
    }

    // ---------------- epilogue ----------------
    const int mb = m0 + warp_m + (lane >> 2);
    #pragma unroll
    for (int im = 0; im < 2; im++) {
        #pragma unroll
        for (int j = 0; j < 8; j++) {
            const int col = n0 + warp_n + j * 8 + (lane & 3) * 2;
            #pragma unroll
            for (int half = 0; half < 2; half++) {
                const int m = mb + im * 16 + half * 8;
                float v0 = acc[im][j][half * 2 + 0] + bias[col];
                float v1 = acc[im][j][half * 2 + 1] + bias[col + 1];
                if (MODE == 0) {
                    const int sct = col >> 9, h = (col >> 6) & 7, d = col & 63;
                    float* dst = (sct == 0) ? g_q : (sct == 1) ? g_k : g_v;
                    if (sct == 0) { v0 *= 0.125f; v1 *= 0.125f; }
                    const int bi = m >> 8, nt = m & 255;
                    float2* dp = (float2*)(dst +
                        (((size_t)(bi * NH + h) * NT + nt) * HDIM + d));
                    *dp = make_float2(v0, v1);
                } else {
                    *(float2*)(outp + (size_t)m * MODEL + col) = make_float2(v0, v1);
                }
            }
        }
    }
}

// ---------------- Kernel: S[bh] = q @ k^T  (256x256, K=64) -----------------
__global__ __launch_bounds__(256) void s_kernel()
{
    __shared__ float As[16][64];
    __shared__ float Bs[16][64];
    const int bh = blockIdx.y;
    const int m0 = (blockIdx.x >> 2) * 64;
    const int n0 = (blockIdx.x & 3) * 64;
    const float* q = g_q + (size_t)bh * NT * HDIM;
    const float* k = g_k + (size_t)bh * NT * HDIM;
    const int tid = threadIdx.x;
    const int tm = (tid >> 4) << 2;
    const int tn = (tid & 15) << 2;
    const int lr = tid >> 2;
    const int lc = (tid & 3) << 2;
    float acc[4][4] = {};
    for (int k0 = 0; k0 < HDIM; k0 += 16) {
        float4 a4 = *(const float4*)(q + (m0 + lr) * HDIM + k0 + lc);
        float4 b4 = *(const float4*)(k + (n0 + lr) * HDIM + k0 + lc);
        As[lc+0][lr]=a4.x; As[lc+1][lr]=a4.y; As[lc+2][lr]=a4.z; As[lc+3][lr]=a4.w;
        Bs[lc+0][lr]=b4.x; Bs[lc+1][lr]=b4.y; Bs[lc+2][lr]=b4.z; Bs[lc+3][lr]=b4.w;
        __syncthreads();
        #pragma unroll
        for (int kk = 0; kk < 16; kk++) {
            float4 av = *(const float4*)&As[kk][tm];
            float4 bv = *(const float4*)&Bs[kk][tn];
            float a[4] = {av.x, av.y, av.z, av.w};
            float b[4] = {bv.x, bv.y, bv.z, bv.w};
            #pragma unroll
            for (int i = 0; i < 4; i++)
                #pragma unroll
                for (int j = 0; j < 4; j++)
                    acc[i][j] = fmaf(a[i], b[j], acc[i][j]);
        }
        __syncthreads();
    }
    float* Sp = g_S + (size_t)bh * NT * NT;
    #pragma unroll
    for (int i = 0; i < 4; i++)
        #pragma unroll
        for (int j = 0; j < 4; j++)
            Sp[(m0 + tm + i) * NT + n0 + tn + j] = acc[i][j];
}

// ---------------- Kernel: conv + bias + softmax -----------------------------
__global__ __launch_bounds__(256) void conv_softmax_kernel(
    const float* __restrict__ pe_w, const float* __restrict__ pe_b,
    const float* __restrict__ rpb)
{
    __shared__ float sr[30][NT];
    const int bh = blockIdx.y;
    const int h  = bh & 7;
    const int i0 = blockIdx.x * 16;
    const float* S = g_S + (size_t)bh * NT * NT;
    float*       P = g_P + (size_t)bh * NT * NT;
    const int tid = threadIdx.x;
    #pragma unroll
    for (int r = 0; r < 30; r++) {
        const int g = i0 - 7 + r;
        sr[r][tid] = (g >= 0 && g < NT) ? S[g * NT + tid] : 0.f;
    }
    __syncthreads();
    float w[15];
    #pragma unroll
    for (int t = 0; t < 15; t++) w[t] = pe_w[h * 15 + t];
    const float pb = pe_b[h];
    const int warp = tid >> 5, lane = tid & 31;
    #pragma unroll
    for (int rr = 0; rr < 2; rr++) {
        const int li = warp * 2 + rr;
        const int ii = i0 + li;
        const int ri = ii >> 4, ci = ii & 15;
        float vals[8];
        #pragma unroll
        for (int e = 0; e < 8; e++) {
            const int j = lane + e * 32;
            float conv = 0.f;
            #pragma unroll
            for (int t = 0; t < 15; t++)
                conv = fmaf(sr[li + t][j], w[t], conv);
            const int rj = j >> 4, cj = j & 15;
            const int idx = (ri - rj + 15) * 31 + (ci - cj + 15);
            vals[e] = sr[li + 7][j] + conv + pb + __ldg(&rpb[idx * 8 + h]);
        }
        float mx = vals[0];
        #pragma unroll
        for (int e = 1; e < 8; e++) mx = fmaxf(mx, vals[e]);
        #pragma unroll
        for (int o = 16; o; o >>= 1) mx = fmaxf(mx, __shfl_xor_sync(0xffffffffu, mx, o));
        float sum = 0.f;
        #pragma unroll
        for (int e = 0; e < 8; e++) { vals[e] = expf(vals[e] - mx); sum += vals[e]; }
        #pragma unroll
        for (int o = 16; o; o >>= 1) sum += __shfl_xor_sync(0xffffffffu, sum, o);
        const float inv = 1.f / sum;
        #pragma unroll
        for (int e = 0; e < 8; e++)
            P[ii * NT + lane + e * 32] = vals[e] * inv;
    }
}

// ---------------- Kernel: O = P @ V, write split into g_ohs -----------------
__global__ __launch_bounds__(256) void av_kernel()
{
    __shared__ float As[16][64];
    __shared__ float Bs[16][64];
    const int bh = blockIdx.y;
    const int m0 = blockIdx.x * 64;
    const float* P = g_P + (size_t)bh * NT * NT;
    const float* V = g_v + (size_t)bh * NT * HDIM;
    const int tid = threadIdx.x;
    const int tm = (tid >> 4) << 2;
    const int tn = (tid & 15) << 2;
    const int lr = tid >> 2;
    const int lc = (tid & 3) << 2;
    const int br = tid >> 4;
    const int bc = (tid & 15) << 2;
    float acc[4][4] = {};
    for (int k0 = 0; k0 < NT; k0 += 16) {
        float4 a4 = *(const float4*)(P + (m0 + lr) * NT + k0 + lc);
        As[lc+0][lr]=a4.x; As[lc+1][lr]=a4.y; As[lc+2][lr]=a4.z; As[lc+3][lr]=a4.w;
        float4 b4 = *(const float4*)(V + (k0 + br) * HDIM + bc);
        *(float4*)&Bs[br][bc] = b4;
        __syncthreads();
        #pragma unroll
        for (int kk = 0; kk < 16; kk++) {
            float4 av = *(const float4*)&As[kk][tm];
            float4 bv = *(const float4*)&Bs[kk][tn];
            float a[4] = {av.x, av.y, av.z, av.w};
            float b[4] = {bv.x, bv.y, bv.z, bv.w};
            #pragma unroll
            for (int i = 0; i < 4; i++)
                #pragma unroll
                for (int j = 0; j < 4; j++)
                    acc[i][j] = fmaf(a[i], b[j], acc[i][j]);
        }
        __syncthreads();
    }
    const int bi = bh >> 3, hh = bh & 7;
    #pragma unroll
    for (int i = 0; i < 4; i++) {
        const int itok = m0 + tm + i;
        #pragma unroll
        for (int j = 0; j < 4; j++) {
            const size_t base = (size_t)(bi * NT + itok) * KX + hh * HDIM + tn + j;
            __nv_bfloat16 hi, lo;
            split1(acc[i][j], hi, lo);
            g_ohs[base] = hi;
            g_ohs[base + 512] = lo;
            g_ohs[base + 1024] = hi;
        }
    }
}

// ---------------------------------------------------------------------------
extern "C" void kernel_launch(void* const* d_in, const int* in_sizes, int n_in,
                              void* d_out, int out_size)
{
    (void)in_sizes; (void)n_in; (void)out_size;
    const float* x      = (const float*)d_in[0];
    const float* qkv_w  = (const float*)d_in[1];
    const float* qkv_b  = (const float*)d_in[2];
    const float* pe_w   = (const float*)d_in[3];
    const float* pe_b   = (const float*)d_in[4];
    const float* rpb    = (const float*)d_in[5];
    const float* proj_w = (const float*)d_in[6];
    const float* proj_b = (const float*)d_in[7];
    float* out = (float*)d_out;

    static bool attr_done = false;
    if (!attr_done) {
        cudaFuncSetAttribute(gemm_mma<0>, cudaFuncAttributeMaxDynamicSharedMemorySize, GSMEM);
        cudaFuncSetAttribute(gemm_mma<1>, cudaFuncAttributeMaxDynamicSharedMemorySize, GSMEM);
        attr_done = true;
    }

    __nv_bfloat16 *xs, *qws, *pws, *ohs;
    cudaGetSymbolAddress((void**)&xs,  g_xs);
    cudaGetSymbolAddress((void**)&qws, g_qws);
    cudaGetSymbolAddress((void**)&pws, g_pws);
    cudaGetSymbolAddress((void**)&ohs, g_ohs);

    split_a_kernel<<<(MTOT * MODEL + 255) / 256, 256>>>(x, xs, MTOT * MODEL);
    split_b_kernel<<<(QKVN * MODEL + 255) / 256, 256>>>(qkv_w, qws, QKVN * MODEL);
    split_b_kernel<<<(MODEL * MODEL + 255) / 256, 256>>>(proj_w, pws, MODEL * MODEL);

    gemm_mma<0><<<dim3(QKVN / BN, MTOT / BM), 256, GSMEM>>>(xs, qws, qkv_b, nullptr);

    s_kernel<<<dim3(16, NBH), 256>>>();
    conv_softmax_kernel<<<dim3(16, NBH), 256>>>(pe_w, pe_b, rpb);
    av_kernel<<<dim3(4, NBH), 256>>>();

    gemm_mma<1><<<dim3(MODEL / BN, MTOT / BM), 256, GSMEM>>>(ohs, pws, proj_b, out);
}

// round 6
// speedup vs baseline: 2.3129x; 1.9072x over previous
#include <cuda_runtime.h>
#include <cuda_bf16.h>
#include <cstdint>

#define BATCH 128
#define NH    8
#define NT    256
#define HDIM  64
#define MODEL 512
#define NBH   (BATCH*NH)    // 1024
#define MTOT  (BATCH*NT)    // 32768
#define QKVN  (3*NH*HDIM)   // 1536
#define KX    1536          // extended K = 3*512

// ---------------- scratch (static __device__, no runtime allocation) -------
__device__ float g_v[(size_t)NBH*NT*HDIM];
__device__ float g_S[(size_t)NBH*NT*NT];
__device__ __nv_bfloat16 g_qe[(size_t)NBH*NT*128];   // [qh|ql] per row (scaled)
__device__ __nv_bfloat16 g_ke[(size_t)NBH*NT*128];   // [kh|kl] per row
__device__ __nv_bfloat16 g_pe[(size_t)NBH*NT*512];   // [Ph|Pl] per row
__device__ __nv_bfloat16 g_vt[(size_t)NBH*64*512];   // [Vh|Vl], V transposed
__device__ __nv_bfloat16 g_xs[(size_t)MTOT*KX];      // [Ah|Al|Ah] of x
__device__ __nv_bfloat16 g_qws[(size_t)QKVN*KX];     // [Bh|Bh|Bl] of qkv_w
__device__ __nv_bfloat16 g_pws[(size_t)MODEL*KX];    // [Bh|Bh|Bl] of proj_w
__device__ __nv_bfloat16 g_ohs[(size_t)MTOT*KX];     // [Ah|Al|Ah] of attn out

// ---------------- helpers ---------------------------------------------------
__device__ __forceinline__ uint32_t smem_u32(const void* p) {
    uint32_t a;
    asm("{ .reg .u64 t; cvta.to.shared.u64 t, %1; cvt.u32.u64 %0, t; }"
        : "=r"(a) : "l"(p));
    return a;
}
__device__ __forceinline__ void cp16(uint32_t s, const void* g) {
    asm volatile("cp.async.cg.shared.global [%0], [%1], 16;" :: "r"(s), "l"(g));
}
#define CP_COMMIT() asm volatile("cp.async.commit_group;")
#define CP_WAIT1()  asm volatile("cp.async.wait_group 1;")
__device__ __forceinline__ void ldm4(uint32_t& r0, uint32_t& r1, uint32_t& r2,
                                     uint32_t& r3, uint32_t a) {
    asm volatile("ldmatrix.sync.aligned.m8n8.x4.shared.b16 {%0,%1,%2,%3}, [%4];"
                 : "=r"(r0), "=r"(r1), "=r"(r2), "=r"(r3) : "r"(a));
}
__device__ __forceinline__ void mma16816(float* c, const uint32_t* a,
                                         uint32_t b0, uint32_t b1) {
    asm volatile(
        "mma.sync.aligned.m16n8k16.row.col.f32.bf16.bf16.f32 "
        "{%0,%1,%2,%3}, {%4,%5,%6,%7}, {%8,%9}, {%0,%1,%2,%3};"
        : "+f"(c[0]), "+f"(c[1]), "+f"(c[2]), "+f"(c[3])
        : "r"(a[0]), "r"(a[1]), "r"(a[2]), "r"(a[3]), "r"(b0), "r"(b1));
}
__device__ __forceinline__ void split1(float v, __nv_bfloat16& h, __nv_bfloat16& l) {
    h = __float2bfloat16(v);
    l = __float2bfloat16(v - __bfloat162float(h));
}

// ---------------- split kernels ---------------------------------------------
__global__ void split_a_kernel(const float* __restrict__ s, __nv_bfloat16* d,
                               int total) {
    int i = blockIdx.x * 256 + threadIdx.x;
    if (i >= total) return;
    int r = i >> 9, k = i & 511;
    __nv_bfloat16 h, l;
    split1(s[i], h, l);
    size_t base = (size_t)r * KX + k;
    d[base] = h; d[base + 512] = l; d[base + 1024] = h;
}
__global__ void split_b_kernel(const float* __restrict__ s, __nv_bfloat16* d,
                               int total) {
    int i = blockIdx.x * 256 + threadIdx.x;
    if (i >= total) return;
    int r = i >> 9, k = i & 511;
    __nv_bfloat16 h, l;
    split1(s[i], h, l);
    size_t base = (size_t)r * KX + k;
    d[base] = h; d[base + 512] = h; d[base + 1024] = l;
}

// ---------------- bf16 mma.sync GEMM (large, dense) -------------------------
#define BM 128
#define BN 128
#define BK 32
#define NSTG 3
#define ROWB 80u                       // padded row: 40 bf16 = 80B
#define STGB (2u * BM * ROWB)          // 20480B
#define GSMEM (NSTG * STGB)            // 61440B

template<int MODE>
__global__ __launch_bounds__(256, 2) void gemm_mma(
    const __nv_bfloat16* __restrict__ gA, const __nv_bfloat16* __restrict__ gB,
    const float* __restrict__ bias, float* __restrict__ outp)
{
    extern __shared__ char smem[];
    const uint32_t sb = smem_u32(smem);
    const int tid = threadIdx.x, wid = tid >> 5, lane = tid & 31;
    const int m0 = blockIdx.y * BM;
    const int n0 = blockIdx.x * BN;
    const int warp_m = (wid & 3) * 32;
    const int warp_n = (wid >> 2) * 64;

    const int c0r = tid >> 2, c0c = (tid & 3) * 8;
    const int c1r = (tid + 256) >> 2, c1c = ((tid + 256) & 3) * 8;

    auto load_stage = [&](int ks, int buf) {
        const size_t kofs = (size_t)ks * BK;
        const uint32_t abase = sb + buf * STGB;
        const uint32_t bbase = abase + BM * ROWB;
        cp16(abase + c0r * ROWB + c0c * 2, gA + (size_t)(m0 + c0r) * KX + kofs + c0c);
        cp16(abase + c1r * ROWB + c1c * 2, gA + (size_t)(m0 + c1r) * KX + kofs + c1c);
        cp16(bbase + c0r * ROWB + c0c * 2, gB + (size_t)(n0 + c0r) * KX + kofs + c0c);
        cp16(bbase + c1r * ROWB + c1c * 2, gB + (size_t)(n0 + c1r) * KX + kofs + c1c);
    };

    const int NK = KX / BK;   // 48
    load_stage(0, 0); CP_COMMIT();
    load_stage(1, 1); CP_COMMIT();

    float acc[2][8][4] = {};
    const int a_row = warp_m + (lane & 15);
    const int a_col = (lane >> 4) * 8;
    const int b_row = warp_n + (lane & 7) + ((lane >> 4) << 3);
    const int b_col = ((lane >> 3) & 1) * 8;

    for (int ks = 0; ks < NK; ks++) {
        CP_WAIT1();
        __syncthreads();
        const int pf = ks + NSTG - 1;
        if (pf < NK) load_stage(pf, pf % NSTG);
        CP_COMMIT();
        const int buf = ks % NSTG;
        const uint32_t abase = sb + buf * STGB;
        const uint32_t bbase = abase + BM * ROWB;
        #pragma unroll
        for (int kk = 0; kk < 2; kk++) {
            uint32_t af[2][4];
            #pragma unroll
            for (int im = 0; im < 2; im++)
                ldm4(af[im][0], af[im][1], af[im][2], af[im][3],
                     abase + (a_row + im * 16) * ROWB + (kk * 16 + a_col) * 2);
            #pragma unroll
            for (int jn = 0; jn < 4; jn++) {
                uint32_t b0, b1, b2, b3;
                ldm4(b0, b1, b2, b3,
                     bbase + (b_row + jn * 16) * ROWB + (kk * 16 + b_col) * 2);
                #pragma unroll
                for (int im = 0; im < 2; im++) {
                    mma16816(acc[im][jn * 2 + 0], af[im], b0, b1);
                    mma16816(acc[im][jn * 2 + 1], af[im], b2, b3);
                }
            }
        }
    }

    const int mb = m0 + warp_m + (lane >> 2);
    #pragma unroll
    for (int im = 0; im < 2; im++) {
        #pragma unroll
        for (int j = 0; j < 8; j++) {
            const int col = n0 + warp_n + j * 8 + (lane & 3) * 2;
            #pragma unroll
            for (int half = 0; half < 2; half++) {
                const int m = mb + im * 16 + half * 8;
                float v0 = acc[im][j][half * 2 + 0] + bias[col];
                float v1 = acc[im][j][half * 2 + 1] + bias[col + 1];
                if (MODE == 0) {
                    const int sct = col >> 9, h = (col >> 6) & 7, d = col & 63;
                    const int bi = m >> 8, nt = m & 255;
                    if (sct == 2) {
                        float2* dp = (float2*)(g_v +
                            (((size_t)(bi * NH + h) * NT + nt) * HDIM + d));
                        *dp = make_float2(v0, v1);
                    } else {
                        if (sct == 0) { v0 *= 0.125f; v1 *= 0.125f; }
                        __nv_bfloat16 h0, l0, h1, l1;
                        split1(v0, h0, l0); split1(v1, h1, l1);
                        __nv_bfloat16* base = ((sct == 0) ? g_qe : g_ke) +
                            ((size_t)(bi * NH + h) * NT + nt) * 128 + d;
                        __nv_bfloat162 th, tl;
                        th.x = h0; th.y = h1; tl.x = l0; tl.y = l1;
                        *(__nv_bfloat162*)(base)      = th;
                        *(__nv_bfloat162*)(base + 64) = tl;
                    }
                } else {
                    *(float2*)(outp + (size_t)m * MODEL + col) = make_float2(v0, v1);
                }
            }
        }
    }
}

// ---------------- s_mma: S[bh] = q_ext @ k_ext^T  (mma.sync) ----------------
// A = g_qe [256][128] ([qh|ql]), B = g_ke [256][128] ([kh|kl])
// 6 stages of 32: terms qh*kh, ql*kh, qh*kl
__global__ __launch_bounds__(256, 2) void s_mma()
{
    extern __shared__ char smem[];
    const uint32_t sb = smem_u32(smem);
    const int tid = threadIdx.x, wid = tid >> 5, lane = tid & 31;
    const int bh = blockIdx.y;
    const int m0 = (blockIdx.x >> 1) * 128;
    const int n0 = (blockIdx.x & 1) * 128;
    const __nv_bfloat16* gA = g_qe + (size_t)bh * NT * 128;
    const __nv_bfloat16* gB = g_ke + (size_t)bh * NT * 128;
    const int warp_m = (wid & 3) * 32;
    const int warp_n = (wid >> 2) * 64;

    const int c0r = tid >> 2, c0c = (tid & 3) * 8;
    const int c1r = (tid + 256) >> 2, c1c = ((tid + 256) & 3) * 8;

    auto aoff = [](int s) { return (s < 4) ? s * 32 : (s - 4) * 32; };
    auto boff = [](int s) { return (s < 4) ? (s & 1) * 32 : (s - 2) * 32; };

    auto load_stage = [&](int ks, int buf) {
        const int ao = aoff(ks), bo = boff(ks);
        const uint32_t abase = sb + buf * STGB;
        const uint32_t bbase = abase + BM * ROWB;
        cp16(abase + c0r * ROWB + c0c * 2, gA + (size_t)(m0 + c0r) * 128 + ao + c0c);
        cp16(abase + c1r * ROWB + c1c * 2, gA + (size_t)(m0 + c1r) * 128 + ao + c1c);
        cp16(bbase + c0r * ROWB + c0c * 2, gB + (size_t)(n0 + c0r) * 128 + bo + c0c);
        cp16(bbase + c1r * ROWB + c1c * 2, gB + (size_t)(n0 + c1r) * 128 + bo + c1c);
    };

    const int NK = 6;
    load_stage(0, 0); CP_COMMIT();
    load_stage(1, 1); CP_COMMIT();

    float acc[2][8][4] = {};
    const int a_row = warp_m + (lane & 15);
    const int a_col = (lane >> 4) * 8;
    const int b_row = warp_n + (lane & 7) + ((lane >> 4) << 3);
    const int b_col = ((lane >> 3) & 1) * 8;

    for (int ks = 0; ks < NK; ks++) {
        CP_WAIT1();
        __syncthreads();
        const int pf = ks + 2;
        if (pf < NK) load_stage(pf, pf % 3);
        CP_COMMIT();
        const int buf = ks % 3;
        const uint32_t abase = sb + buf * STGB;
        const uint32_t bbase = abase + BM * ROWB;
        #pragma unroll
        for (int kk = 0; kk < 2; kk++) {
            uint32_t af[2][4];
            #pragma unroll
            for (int im = 0; im < 2; im++)
                ldm4(af[im][0], af[im][1], af[im][2], af[im][3],
                     abase + (a_row + im * 16) * ROWB + (kk * 16 + a_col) * 2);
            #pragma unroll
            for (int jn = 0; jn < 4; jn++) {
                uint32_t b0, b1, b2, b3;
                ldm4(b0, b1, b2, b3,
                     bbase + (b_row + jn * 16) * ROWB + (kk * 16 + b_col) * 2);
                #pragma unroll
                for (int im = 0; im < 2; im++) {
                    mma16816(acc[im][jn * 2 + 0], af[im], b0, b1);
                    mma16816(acc[im][jn * 2 + 1], af[im], b2, b3);
                }
            }
        }
    }

    float* Sp = g_S + (size_t)bh * NT * NT;
    const int mb = m0 + warp_m + (lane >> 2);
    #pragma unroll
    for (int im = 0; im < 2; im++) {
        #pragma unroll
        for (int j = 0; j < 8; j++) {
            const int col = n0 + warp_n + j * 8 + (lane & 3) * 2;
            #pragma unroll
            for (int half = 0; half < 2; half++) {
                const int m = mb + im * 16 + half * 8;
                *(float2*)(Sp + (size_t)m * NT + col) =
                    make_float2(acc[im][j][half * 2], acc[im][j][half * 2 + 1]);
            }
        }
    }
}

// ---------------- vt_kernel: transpose + split V ----------------------------
__global__ __launch_bounds__(256) void vt_kernel()
{
    __shared__ float sv[128 * 65];
    const int bh = blockIdx.x, tid = threadIdx.x;
    const float* V = g_v + (size_t)bh * NT * HDIM;
    __nv_bfloat16* dst = g_vt + (size_t)bh * 64 * 512;
    for (int pass = 0; pass < 2; pass++) {
        const int kbase = pass * 128;
        for (int i = tid; i < 128 * 64; i += 256) {
            int k2 = i >> 6, n = i & 63;
            sv[k2 * 65 + n] = V[(size_t)(kbase + k2) * 64 + n];
        }
        __syncthreads();
        const int n = tid >> 2, q = tid & 3;
        for (int kk = 0; kk < 32; kk += 2) {
            const int k2 = q * 32 + kk;
            float v0 = sv[k2 * 65 + n], v1 = sv[(k2 + 1) * 65 + n];
            __nv_bfloat16 h0, l0, h1, l1;
            split1(v0, h0, l0); split1(v1, h1, l1);
            __nv_bfloat162 th, tl;
            th.x = h0; th.y = h1; tl.x = l0; tl.y = l1;
            const int k = kbase + k2;
            *(__nv_bfloat162*)(dst + (size_t)n * 512 + k)       = th;
            *(__nv_bfloat162*)(dst + (size_t)n * 512 + 256 + k) = tl;
        }
        __syncthreads();
    }
}

// ---------------- conv + bias + softmax -> split P --------------------------
__global__ __launch_bounds__(256) void conv_softmax_kernel(
    const float* __restrict__ pe_w, const float* __restrict__ pe_b,
    const float* __restrict__ rpb)
{
    __shared__ float sr[30][NT];
    const int bh = blockIdx.y;
    const int h  = bh & 7;
    const int i0 = blockIdx.x * 16;
    const float* S = g_S + (size_t)bh * NT * NT;
    __nv_bfloat16* pe = g_pe + (size_t)bh * NT * 512;
    const int tid = threadIdx.x;
    #pragma unroll
    for (int r = 0; r < 30; r++) {
        const int g = i0 - 7 + r;
        sr[r][tid] = (g >= 0 && g < NT) ? S[g * NT + tid] : 0.f;
    }
    __syncthreads();
    float w[15];
    #pragma unroll
    for (int t = 0; t < 15; t++) w[t] = pe_w[h * 15 + t];
    const float pb = pe_b[h];
    const int warp = tid >> 5, lane = tid & 31;
    #pragma unroll
    for (int rr = 0; rr < 2; rr++) {
        const int li = warp * 2 + rr;
        const int ii = i0 + li;
        const int ri = ii >> 4, ci = ii & 15;
        float vals[8];
        #pragma unroll
        for (int e = 0; e < 8; e++) {
            const int j = lane + e * 32;
            float conv = 0.f;
            #pragma unroll
            for (int t = 0; t < 15; t++)
                conv = fmaf(sr[li + t][j], w[t], conv);
            const int rj = j >> 4, cj = j & 15;
            const int idx = (ri - rj + 15) * 31 + (ci - cj + 15);
            vals[e] = sr[li + 7][j] + conv + pb + __ldg(&rpb[idx * 8 + h]);
        }
        float mx = vals[0];
        #pragma unroll
        for (int e = 1; e < 8; e++) mx = fmaxf(mx, vals[e]);
        #pragma unroll
        for (int o = 16; o; o >>= 1) mx = fmaxf(mx, __shfl_xor_sync(0xffffffffu, mx, o));
        float sum = 0.f;
        #pragma unroll
        for (int e = 0; e < 8; e++) { vals[e] = expf(vals[e] - mx); sum += vals[e]; }
        #pragma unroll
        for (int o = 16; o; o >>= 1) sum += __shfl_xor_sync(0xffffffffu, sum, o);
        const float inv = 1.f / sum;
        #pragma unroll
        for (int e = 0; e < 8; e++) {
            const int j = lane + e * 32;
            float pv = vals[e] * inv;
            __nv_bfloat16 hh, ll;
            split1(pv, hh, ll);
            pe[(size_t)ii * 512 + j]       = hh;
            pe[(size_t)ii * 512 + 256 + j] = ll;
        }
    }
}

// ---------------- av_mma: O[bh] = P_ext @ V_ext^T ---------------------------
// A = g_pe [256][512] ([Ph|Pl]), B = g_vt [64][512] ([Vh|Vl])
// 24 stages of 32: terms Ph*Vh, Pl*Vh, Ph*Vl.  Output -> g_ohs (3-seg)
#define AV_ASZ (256u * ROWB)      // 20480
#define AV_STG (AV_ASZ + 64u * ROWB)   // 25600
#define AVSMEM (3u * AV_STG)      // 76800

__global__ __launch_bounds__(256, 2) void av_mma()
{
    extern __shared__ char smem[];
    const uint32_t sb = smem_u32(smem);
    const int tid = threadIdx.x, wid = tid >> 5, lane = tid & 31;
    const int bh = blockIdx.x;
    const __nv_bfloat16* gA = g_pe + (size_t)bh * NT * 512;
    const __nv_bfloat16* gB = g_vt + (size_t)bh * 64 * 512;
    const int warp_m = (wid & 3) * 64;
    const int warp_n = (wid >> 2) * 32;

    auto aoff = [](int s) { return s < 8 ? s * 32 : s < 16 ? 256 + (s - 8) * 32
                                                           : (s - 16) * 32; };
    auto boff = [](int s) { return s < 8 ? s * 32 : s < 16 ? (s - 8) * 32
                                                           : 256 + (s - 16) * 32; };

    auto load_stage = [&](int ks, int buf) {
        const int ao = aoff(ks), bo = boff(ks);
        const uint32_t abase = sb + buf * AV_STG;
        const uint32_t bbase = abase + AV_ASZ;
        #pragma unroll
        for (int t = 0; t < 5; t++) {
            const int idx = tid + t * 256;
            if (idx < 1024) {
                const int r = idx >> 2, c = (idx & 3) * 8;
                cp16(abase + r * ROWB + c * 2, gA + (size_t)r * 512 + ao + c);
            } else {
                const int j = idx - 1024;
                const int r = j >> 2, c = (j & 3) * 8;
                cp16(bbase + r * ROWB + c * 2, gB + (size_t)r * 512 + bo + c);
            }
        }
    };

    const int NK = 24;
    load_stage(0, 0); CP_COMMIT();
    load_stage(1, 1); CP_COMMIT();

    float acc[4][4][4] = {};
    const int a_row = warp_m + (lane & 15);
    const int a_col = (lane >> 4) * 8;
    const int b_row = warp_n + (lane & 7) + ((lane >> 4) << 3);
    const int b_col = ((lane >> 3) & 1) * 8;

    for (int ks = 0; ks < NK; ks++) {
        CP_WAIT1();
        __syncthreads();
        const int pf = ks + 2;
        if (pf < NK) load_stage(pf, pf % 3);
        CP_COMMIT();
        const int buf = ks % 3;
        const uint32_t abase = sb + buf * AV_STG;
        const uint32_t bbase = abase + AV_ASZ;
        #pragma unroll
        for (int kk = 0; kk < 2; kk++) {
            uint32_t af[4][4];
            #pragma unroll
            for (int im = 0; im < 4; im++)
                ldm4(af[im][0], af[im][1], af[im][2], af[im][3],
                     abase + (a_row + im * 16) * ROWB + (kk * 16 + a_col) * 2);
            #pragma unroll
            for (int jn = 0; jn < 2; jn++) {
                uint32_t b0, b1, b2, b3;
                ldm4(b0, b1, b2, b3,
                     bbase + (b_row + jn * 16) * ROWB + (kk * 16 + b_col) * 2);
                #pragma unroll
                for (int im = 0; im < 4; im++) {
                    mma16816(acc[im][jn * 2 + 0], af[im], b0, b1);
                    mma16816(acc[im][jn * 2 + 1], af[im], b2, b3);
                }
            }
        }
    }

    const int bi = bh >> 3, hh = bh & 7;
    #pragma unroll
    for (int im = 0; im < 4; im++) {
        #pragma unroll
        for (int j = 0; j < 4; j++) {
            const int col = warp_n + j * 8 + (lane & 3) * 2;   // 0..63
            #pragma unroll
            for (int half = 0; half < 2; half++) {
                const int m = warp_m + im * 16 + (lane >> 2) + half * 8;
                float v0 = acc[im][j][half * 2 + 0];
                float v1 = acc[im][j][half * 2 + 1];
                __nv_bfloat16 h0, l0, h1, l1;
                split1(v0, h0, l0); split1(v1, h1, l1);
                __nv_bfloat162 th, tl;
                th.x = h0; th.y = h1; tl.x = l0; tl.y = l1;
                __nv_bfloat16* base = g_ohs + (size_t)(bi * NT + m) * KX + hh * 64 + col;
                *(__nv_bfloat162*)(base)        = th;
                *(__nv_bfloat162*)(base + 512)  = tl;
                *(__nv_bfloat162*)(base + 1024) = th;
            }
        }
    }
}

// ---------------------------------------------------------------------------
extern "C" void kernel_launch(void* const* d_in, const int* in_sizes, int n_in,
                              void* d_out, int out_size)
{
    (void)in_sizes; (void)n_in; (void)out_size;
    const float* x      = (const float*)d_in[0];
    const float* qkv_w  = (const float*)d_in[1];
    const float* qkv_b  = (const float*)d_in[2];
    const float* pe_w   = (const float*)d_in[3];
    const float* pe_b   = (const float*)d_in[4];
    const float* rpb    = (const float*)d_in[5];
    const float* proj_w = (const float*)d_in[6];
    const float* proj_b = (const float*)d_in[7];
    float* out = (float*)d_out;

    static bool attr_done = false;
    if (!attr_done) {
        cudaFuncSetAttribute(gemm_mma<0>, cudaFuncAttributeMaxDynamicSharedMemorySize, GSMEM);
        cudaFuncSetAttribute(gemm_mma<1>, cudaFuncAttributeMaxDynamicSharedMemorySize, GSMEM);
        cudaFuncSetAttribute(s_mma, cudaFuncAttributeMaxDynamicSharedMemorySize, GSMEM);
        cudaFuncSetAttribute(av_mma, cudaFuncAttributeMaxDynamicSharedMemorySize, AVSMEM);
        attr_done = true;
    }

    __nv_bfloat16 *xs, *qws, *pws, *ohs;
    cudaGetSymbolAddress((void**)&xs,  g_xs);
    cudaGetSymbolAddress((void**)&qws, g_qws);
    cudaGetSymbolAddress((void**)&pws, g_pws);
    cudaGetSymbolAddress((void**)&ohs, g_ohs);

    split_a_kernel<<<(MTOT * MODEL + 255) / 256, 256>>>(x, xs, MTOT * MODEL);
    split_b_kernel<<<(QKVN * MODEL + 255) / 256, 256>>>(qkv_w, qws, QKVN * MODEL);
    split_b_kernel<<<(MODEL * MODEL + 255) / 256, 256>>>(proj_w, pws, MODEL * MODEL);

    gemm_mma<0><<<dim3(QKVN / BN, MTOT / BM), 256, GSMEM>>>(xs, qws, qkv_b, nullptr);

    vt_kernel<<<NBH, 256>>>();
    s_mma<<<dim3(4, NBH), 256, GSMEM>>>();
    conv_softmax_kernel<<<dim3(16, NBH), 256>>>(pe_w, pe_b, rpb);
    av_mma<<<NBH, 256, AVSMEM>>>();

    gemm_mma<1><<<dim3(MODEL / BN, MTOT / BM), 256, GSMEM>>>(ohs, pws, proj_b, out);
}

// round 7
// speedup vs baseline: 2.5513x; 1.1031x over previous
#include <cuda_runtime.h>
#include <cuda_bf16.h>
#include <cstdint>

#define BATCH 128
#define NH    8
#define NT    256
#define HDIM  64
#define MODEL 512
#define NBH   (BATCH*NH)    // 1024
#define MTOT  (BATCH*NT)    // 32768
#define QKVN  (3*NH*HDIM)   // 1536
#define KX    1536          // extended K = 3*512

// ---------------- scratch (static __device__, no runtime allocation) -------
__device__ float g_v[(size_t)NBH*NT*HDIM];
__device__ float g_S[(size_t)NBH*NT*NT];
__device__ __nv_bfloat16 g_qe[(size_t)NBH*NT*128];   // [qh|ql] per row (scaled)
__device__ __nv_bfloat16 g_ke[(size_t)NBH*NT*128];   // [kh|kl] per row
__device__ __nv_bfloat16 g_pe[(size_t)NBH*NT*512];   // [Ph|Pl] per row
__device__ __nv_bfloat16 g_vt[(size_t)NBH*64*512];   // [Vh|Vl], V transposed
__device__ __nv_bfloat16 g_xs[(size_t)MTOT*KX];      // [Ah|Al|Ah] of x
__device__ __nv_bfloat16 g_qws[(size_t)QKVN*KX];     // [Bh|Bh|Bl] of qkv_w
__device__ __nv_bfloat16 g_pws[(size_t)MODEL*KX];    // [Bh|Bh|Bl] of proj_w
__device__ __nv_bfloat16 g_ohs[(size_t)MTOT*KX];     // [Ah|Al|Ah] of attn out

// ---------------- helpers ---------------------------------------------------
__device__ __forceinline__ uint32_t smem_u32(const void* p) {
    uint32_t a;
    asm("{ .reg .u64 t; cvta.to.shared.u64 t, %1; cvt.u32.u64 %0, t; }"
        : "=r"(a) : "l"(p));
    return a;
}
__device__ __forceinline__ void cp16(uint32_t s, const void* g) {
    asm volatile("cp.async.cg.shared.global [%0], [%1], 16;" :: "r"(s), "l"(g));
}
#define CP_COMMIT() asm volatile("cp.async.commit_group;")
#define CP_WAIT1()  asm volatile("cp.async.wait_group 1;")
__device__ __forceinline__ void ldm4(uint32_t& r0, uint32_t& r1, uint32_t& r2,
                                     uint32_t& r3, uint32_t a) {
    asm volatile("ldmatrix.sync.aligned.m8n8.x4.shared.b16 {%0,%1,%2,%3}, [%4];"
                 : "=r"(r0), "=r"(r1), "=r"(r2), "=r"(r3) : "r"(a));
}
__device__ __forceinline__ void mma16816(float* c, const uint32_t* a,
                                         uint32_t b0, uint32_t b1) {
    asm volatile(
        "mma.sync.aligned.m16n8k16.row.col.f32.bf16.bf16.f32 "
        "{%0,%1,%2,%3}, {%4,%5,%6,%7}, {%8,%9}, {%0,%1,%2,%3};"
        : "+f"(c[0]), "+f"(c[1]), "+f"(c[2]), "+f"(c[3])
        : "r"(a[0]), "r"(a[1]), "r"(a[2]), "r"(a[3]), "r"(b0), "r"(b1));
}
__device__ __forceinline__ void split1(float v, __nv_bfloat16& h, __nv_bfloat16& l) {
    h = __float2bfloat16(v);
    l = __float2bfloat16(v - __bfloat162float(h));
}

// ---------------- split kernels (vectorized x2) -----------------------------
__global__ void split_a_kernel(const float* __restrict__ s, __nv_bfloat16* d,
                               int totpairs) {
    int i = blockIdx.x * 256 + threadIdx.x;
    if (i >= totpairs) return;
    int r = i >> 8, kp = i & 255;          // 256 pairs per 512-row
    float2 v = ((const float2*)s)[i];
    __nv_bfloat16 h0, l0, h1, l1;
    split1(v.x, h0, l0); split1(v.y, h1, l1);
    __nv_bfloat162 th, tl; th.x = h0; th.y = h1; tl.x = l0; tl.y = l1;
    __nv_bfloat162* base = (__nv_bfloat162*)(d + (size_t)r * KX) + kp;
    base[0] = th; base[256] = tl; base[512] = th;
}
__global__ void split_b_kernel(const float* __restrict__ s, __nv_bfloat16* d,
                               int totpairs) {
    int i = blockIdx.x * 256 + threadIdx.x;
    if (i >= totpairs) return;
    int r = i >> 8, kp = i & 255;
    float2 v = ((const float2*)s)[i];
    __nv_bfloat16 h0, l0, h1, l1;
    split1(v.x, h0, l0); split1(v.y, h1, l1);
    __nv_bfloat162 th, tl; th.x = h0; th.y = h1; tl.x = l0; tl.y = l1;
    __nv_bfloat162* base = (__nv_bfloat162*)(d + (size_t)r * KX) + kp;
    base[0] = th; base[256] = th; base[512] = tl;
}

// ---------------- bf16 mma.sync GEMM (large, dense) -------------------------
#define BM 128
#define BN 128
#define BK 32
#define NSTG 3
#define ROWB 80u                       // padded row: 40 bf16 = 80B
#define STGB (2u * BM * ROWB)          // 20480B
#define GSMEM (NSTG * STGB)            // 61440B

template<int MODE>
__global__ __launch_bounds__(256, 2) void gemm_mma(
    const __nv_bfloat16* __restrict__ gA, const __nv_bfloat16* __restrict__ gB,
    const float* __restrict__ bias, float* __restrict__ outp)
{
    extern __shared__ char smem[];
    const uint32_t sb = smem_u32(smem);
    const int tid = threadIdx.x, wid = tid >> 5, lane = tid & 31;
    const int m0 = blockIdx.y * BM;
    const int n0 = blockIdx.x * BN;
    const int warp_m = (wid & 3) * 32;
    const int warp_n = (wid >> 2) * 64;

    const int c0r = tid >> 2, c0c = (tid & 3) * 8;
    const int c1r = (tid + 256) >> 2, c1c = ((tid + 256) & 3) * 8;

    auto load_stage = [&](int ks, int buf) {
        const size_t kofs = (size_t)ks * BK;
        const uint32_t abase = sb + buf * STGB;
        const uint32_t bbase = abase + BM * ROWB;
        cp16(abase + c0r * ROWB + c0c * 2, gA + (size_t)(m0 + c0r) * KX + kofs + c0c);
        cp16(abase + c1r * ROWB + c1c * 2, gA + (size_t)(m0 + c1r) * KX + kofs + c1c);
        cp16(bbase + c0r * ROWB + c0c * 2, gB + (size_t)(n0 + c0r) * KX + kofs + c0c);
        cp16(bbase + c1r * ROWB + c1c * 2, gB + (size_t)(n0 + c1r) * KX + kofs + c1c);
    };

    const int NK = KX / BK;   // 48
    load_stage(0, 0); CP_COMMIT();
    load_stage(1, 1); CP_COMMIT();

    float acc[2][8][4] = {};
    const int a_row = warp_m + (lane & 15);
    const int a_col = (lane >> 4) * 8;
    const int b_row = warp_n + (lane & 7) + ((lane >> 4) << 3);
    const int b_col = ((lane >> 3) & 1) * 8;

    for (int ks = 0; ks < NK; ks++) {
        CP_WAIT1();
        __syncthreads();
        const int pf = ks + NSTG - 1;
        if (pf < NK) load_stage(pf, pf % NSTG);
        CP_COMMIT();
        const int buf = ks % NSTG;
        const uint32_t abase = sb + buf * STGB;
        const uint32_t bbase = abase + BM * ROWB;
        #pragma unroll
        for (int kk = 0; kk < 2; kk++) {
            uint32_t af[2][4], bfr[4][4];
            #pragma unroll
            for (int im = 0; im < 2; im++)
                ldm4(af[im][0], af[im][1], af[im][2], af[im][3],
                     abase + (a_row + im * 16) * ROWB + (kk * 16 + a_col) * 2);
            #pragma unroll
            for (int jn = 0; jn < 4; jn++)
                ldm4(bfr[jn][0], bfr[jn][1], bfr[jn][2], bfr[jn][3],
                     bbase + (b_row + jn * 16) * ROWB + (kk * 16 + b_col) * 2);
            #pragma unroll
            for (int jn = 0; jn < 4; jn++)
                #pragma unroll
                for (int im = 0; im < 2; im++) {
                    mma16816(acc[im][jn * 2 + 0], af[im], bfr[jn][0], bfr[jn][1]);
                    mma16816(acc[im][jn * 2 + 1], af[im], bfr[jn][2], bfr[jn][3]);
                }
        }
    }

    const int mb = m0 + warp_m + (lane >> 2);
    #pragma unroll
    for (int im = 0; im < 2; im++) {
        #pragma unroll
        for (int j = 0; j < 8; j++) {
            const int col = n0 + warp_n + j * 8 + (lane & 3) * 2;
            #pragma unroll
            for (int half = 0; half < 2; half++) {
                const int m = mb + im * 16 + half * 8;
                float v0 = acc[im][j][half * 2 + 0] + bias[col];
                float v1 = acc[im][j][half * 2 + 1] + bias[col + 1];
                if (MODE == 0) {
                    const int sct = col >> 9, h = (col >> 6) & 7, d = col & 63;
                    const int bi = m >> 8, nt = m & 255;
                    if (sct == 2) {
                        float2* dp = (float2*)(g_v +
                            (((size_t)(bi * NH + h) * NT + nt) * HDIM + d));
                        *dp = make_float2(v0, v1);
                    } else {
                        if (sct == 0) { v0 *= 0.125f; v1 *= 0.125f; }
                        __nv_bfloat16 h0, l0, h1, l1;
                        split1(v0, h0, l0); split1(v1, h1, l1);
                        __nv_bfloat16* base = ((sct == 0) ? g_qe : g_ke) +
                            ((size_t)(bi * NH + h) * NT + nt) * 128 + d;
                        __nv_bfloat162 th, tl;
                        th.x = h0; th.y = h1; tl.x = l0; tl.y = l1;
                        *(__nv_bfloat162*)(base)      = th;
                        *(__nv_bfloat162*)(base + 64) = tl;
                    }
                } else {
                    *(float2*)(outp + (size_t)m * MODEL + col) = make_float2(v0, v1);
                }
            }
        }
    }
}

// ---------------- s_mma: S[bh] = q_ext @ k_ext^T  (mma.sync) ----------------
__global__ __launch_bounds__(256, 2) void s_mma()
{
    extern __shared__ char smem[];
    const uint32_t sb = smem_u32(smem);
    const int tid = threadIdx.x, wid = tid >> 5, lane = tid & 31;
    const int bh = blockIdx.y;
    const int m0 = (blockIdx.x >> 1) * 128;
    const int n0 = (blockIdx.x & 1) * 128;
    const __nv_bfloat16* gA = g_qe + (size_t)bh * NT * 128;
    const __nv_bfloat16* gB = g_ke + (size_t)bh * NT * 128;
    const int warp_m = (wid & 3) * 32;
    const int warp_n = (wid >> 2) * 64;

    const int c0r = tid >> 2, c0c = (tid & 3) * 8;
    const int c1r = (tid + 256) >> 2, c1c = ((tid + 256) & 3) * 8;

    auto aoff = [](int s) { return (s < 4) ? s * 32 : (s - 4) * 32; };
    auto boff = [](int s) { return (s < 4) ? (s & 1) * 32 : (s - 2) * 32; };

    auto load_stage = [&](int ks, int buf) {
        const int ao = aoff(ks), bo = boff(ks);
        const uint32_t abase = sb + buf * STGB;
        const uint32_t bbase = abase + BM * ROWB;
        cp16(abase + c0r * ROWB + c0c * 2, gA + (size_t)(m0 + c0r) * 128 + ao + c0c);
        cp16(abase + c1r * ROWB + c1c * 2, gA + (size_t)(m0 + c1r) * 128 + ao + c1c);
        cp16(bbase + c0r * ROWB + c0c * 2, gB + (size_t)(n0 + c0r) * 128 + bo + c0c);
        cp16(bbase + c1r * ROWB + c1c * 2, gB + (size_t)(n0 + c1r) * 128 + bo + c1c);
    };

    const int NK = 6;
    load_stage(0, 0); CP_COMMIT();
    load_stage(1, 1); CP_COMMIT();

    float acc[2][8][4] = {};
    const int a_row = warp_m + (lane & 15);
    const int a_col = (lane >> 4) * 8;
    const int b_row = warp_n + (lane & 7) + ((lane >> 4) << 3);
    const int b_col = ((lane >> 3) & 1) * 8;

    for (int ks = 0; ks < NK; ks++) {
        CP_WAIT1();
        __syncthreads();
        const int pf = ks + 2;
        if (pf < NK) load_stage(pf, pf % 3);
        CP_COMMIT();
        const int buf = ks % 3;
        const uint32_t abase = sb + buf * STGB;
        const uint32_t bbase = abase + BM * ROWB;
        #pragma unroll
        for (int kk = 0; kk < 2; kk++) {
            uint32_t af[2][4], bfr[4][4];
            #pragma unroll
            for (int im = 0; im < 2; im++)
                ldm4(af[im][0], af[im][1], af[im][2], af[im][3],
                     abase + (a_row + im * 16) * ROWB + (kk * 16 + a_col) * 2);
            #pragma unroll
            for (int jn = 0; jn < 4; jn++)
                ldm4(bfr[jn][0], bfr[jn][1], bfr[jn][2], bfr[jn][3],
                     bbase + (b_row + jn * 16) * ROWB + (kk * 16 + b_col) * 2);
            #pragma unroll
            for (int jn = 0; jn < 4; jn++)
                #pragma unroll
                for (int im = 0; im < 2; im++) {
                    mma16816(acc[im][jn * 2 + 0], af[im], bfr[jn][0], bfr[jn][1]);
                    mma16816(acc[im][jn * 2 + 1], af[im], bfr[jn][2], bfr[jn][3]);
                }
        }
    }

    float* Sp = g_S + (size_t)bh * NT * NT;
    const int mb = m0 + warp_m + (lane >> 2);
    #pragma unroll
    for (int im = 0; im < 2; im++) {
        #pragma unroll
        for (int j = 0; j < 8; j++) {
            const int col = n0 + warp_n + j * 8 + (lane & 3) * 2;
            #pragma unroll
            for (int half = 0; half < 2; half++) {
                const int m = mb + im * 16 + half * 8;
                *(float2*)(Sp + (size_t)m * NT + col) =
                    make_float2(acc[im][j][half * 2], acc[im][j][half * 2 + 1]);
            }
        }
    }
}

// ---------------- vt_kernel: transpose + split V ----------------------------
__global__ __launch_bounds__(256) void vt_kernel()
{
    __shared__ float sv[128 * 65];
    const int bh = blockIdx.x, tid = threadIdx.x;
    const float* V = g_v + (size_t)bh * NT * HDIM;
    __nv_bfloat16* dst = g_vt + (size_t)bh * 64 * 512;
    for (int pass = 0; pass < 2; pass++) {
        const int kbase = pass * 128;
        for (int i = tid; i < 128 * 64; i += 256) {
            int k2 = i >> 6, n = i & 63;
            sv[k2 * 65 + n] = V[(size_t)(kbase + k2) * 64 + n];
        }
        __syncthreads();
        const int n = tid >> 2, q = tid & 3;
        for (int kk = 0; kk < 32; kk += 2) {
            const int k2 = q * 32 + kk;
            float v0 = sv[k2 * 65 + n], v1 = sv[(k2 + 1) * 65 + n];
            __nv_bfloat16 h0, l0, h1, l1;
            split1(v0, h0, l0); split1(v1, h1, l1);
            __nv_bfloat162 th, tl;
            th.x = h0; th.y = h1; tl.x = l0; tl.y = l1;
            const int k = kbase + k2;
            *(__nv_bfloat162*)(dst + (size_t)n * 512 + k)       = th;
            *(__nv_bfloat162*)(dst + (size_t)n * 512 + 256 + k) = tl;
        }
        __syncthreads();
    }
}

// ---------------- conv + bias + softmax -> split P --------------------------
// Register sliding-window conv (thread = column), smem staging, warp softmax.
__global__ __launch_bounds__(256) void conv_softmax_kernel(
    const float* __restrict__ pe_w, const float* __restrict__ pe_b,
    const float* __restrict__ rpb)
{
    __shared__ float st[16][NT];
    const int bh = blockIdx.y;
    const int h  = bh & 7;
    const int i0 = blockIdx.x * 16;
    const float* S = g_S + (size_t)bh * NT * NT;
    __nv_bfloat16* pe = g_pe + (size_t)bh * NT * 512;
    const int j = threadIdx.x;

    float win[30];
    #pragma unroll
    for (int r = 0; r < 30; r++) {
        const int g = i0 - 7 + r;
        win[r] = (g >= 0 && g < NT) ? S[(size_t)g * NT + j] : 0.f;
    }
    float w[15];
    #pragma unroll
    for (int t = 0; t < 15; t++) w[t] = pe_w[h * 15 + t];
    const float pb = pe_b[h];
    const int rj = j >> 4, cj = j & 15;

    #pragma unroll
    for (int li = 0; li < 16; li++) {
        float conv = 0.f;
        #pragma unroll
        for (int t = 0; t < 15; t++)
            conv = fmaf(win[li + t], w[t], conv);
        const int ii = i0 + li;
        const int ri = ii >> 4, ci = ii & 15;
        const int idx = (ri - rj + 15) * 31 + (ci - cj + 15);
        st[li][j] = win[li + 7] + conv + pb + __ldg(&rpb[idx * 8 + h]);
    }
    __syncthreads();

    const int warp = j >> 5, lane = j & 31;
    #pragma unroll
    for (int rr = 0; rr < 2; rr++) {
        const int li = warp * 2 + rr;
        const int ii = i0 + li;
        float vals[8];
        #pragma unroll
        for (int e = 0; e < 8; e++) vals[e] = st[li][lane + e * 32];
        float mx = vals[0];
        #pragma unroll
        for (int e = 1; e < 8; e++) mx = fmaxf(mx, vals[e]);
        #pragma unroll
        for (int o = 16; o; o >>= 1) mx = fmaxf(mx, __shfl_xor_sync(0xffffffffu, mx, o));
        float sum = 0.f;
        #pragma unroll
        for (int e = 0; e < 8; e++) { vals[e] = expf(vals[e] - mx); sum += vals[e]; }
        #pragma unroll
        for (int o = 16; o; o >>= 1) sum += __shfl_xor_sync(0xffffffffu, sum, o);
        const float inv = 1.f / sum;
        #pragma unroll
        for (int e = 0; e < 8; e++) {
            const int jj = lane + e * 32;
            float pv = vals[e] * inv;
            __nv_bfloat16 hh, ll;
            split1(pv, hh, ll);
            pe[(size_t)ii * 512 + jj]       = hh;
            pe[(size_t)ii * 512 + 256 + jj] = ll;
        }
    }
}

// ---------------- av_mma: O[bh] = P_ext @ V_ext^T ---------------------------
#define AV_ASZ (256u * ROWB)           // 20480
#define AV_STG (AV_ASZ + 64u * ROWB)   // 25600
#define AVSMEM (3u * AV_STG)           // 76800

__global__ __launch_bounds__(256, 2) void av_mma()
{
    extern __shared__ char smem[];
    const uint32_t sb = smem_u32(smem);
    const int tid = threadIdx.x, wid = tid >> 5, lane = tid & 31;
    const int bh = blockIdx.x;
    const __nv_bfloat16* gA = g_pe + (size_t)bh * NT * 512;
    const __nv_bfloat16* gB = g_vt + (size_t)bh * 64 * 512;
    const int warp_m = (wid & 3) * 64;
    const int warp_n = (wid >> 2) * 32;

    auto aoff = [](int s) { return s < 8 ? s * 32 : s < 16 ? 256 + (s - 8) * 32
                                                           : (s - 16) * 32; };
    auto boff = [](int s) { return s < 8 ? s * 32 : s < 16 ? (s - 8) * 32
                                                           : 256 + (s - 16) * 32; };

    auto load_stage = [&](int ks, int buf) {
        const int ao = aoff(ks), bo = boff(ks);
        const uint32_t abase = sb + buf * AV_STG;
        const uint32_t bbase = abase + AV_ASZ;
        #pragma unroll
        for (int t = 0; t < 5; t++) {
            const int idx = tid + t * 256;
            if (idx < 1024) {
                const int r = idx >> 2, c = (idx & 3) * 8;
                cp16(abase + r * ROWB + c * 2, gA + (size_t)r * 512 + ao + c);
            } else {
                const int jx = idx - 1024;
                const int r = jx >> 2, c = (jx & 3) * 8;
                cp16(bbase + r * ROWB + c * 2, gB + (size_t)r * 512 + bo + c);
            }
        }
    };

    const int NK = 24;
    load_stage(0, 0); CP_COMMIT();
    load_stage(1, 1); CP_COMMIT();

    float acc[4][4][4] = {};
    const int a_row = warp_m + (lane & 15);
    const int a_col = (lane >> 4) * 8;
    const int b_row = warp_n + (lane & 7) + ((lane >> 4) << 3);
    const int b_col = ((lane >> 3) & 1) * 8;

    for (int ks = 0; ks < NK; ks++) {
        CP_WAIT1();
        __syncthreads();
        const int pf = ks + 2;
        if (pf < NK) load_stage(pf, pf % 3);
        CP_COMMIT();
        const int buf = ks % 3;
        const uint32_t abase = sb + buf * AV_STG;
        const uint32_t bbase = abase + AV_ASZ;
        #pragma unroll
        for (int kk = 0; kk < 2; kk++) {
            uint32_t af[4][4], bfr[2][4];
            #pragma unroll
            for (int im = 0; im < 4; im++)
                ldm4(af[im][0], af[im][1], af[im][2], af[im][3],
                     abase + (a_row + im * 16) * ROWB + (kk * 16 + a_col) * 2);
            #pragma unroll
            for (int jn = 0; jn < 2; jn++)
                ldm4(bfr[jn][0], bfr[jn][1], bfr[jn][2], bfr[jn][3],
                     bbase + (b_row + jn * 16) * ROWB + (kk * 16 + b_col) * 2);
            #pragma unroll
            for (int jn = 0; jn < 2; jn++)
                #pragma unroll
                for (int im = 0; im < 4; im++) {
                    mma16816(acc[im][jn * 2 + 0], af[im], bfr[jn][0], bfr[jn][1]);
                    mma16816(acc[im][jn * 2 + 1], af[im], bfr[jn][2], bfr[jn][3]);
                }
        }
    }

    const int bi = bh >> 3, hh = bh & 7;
    #pragma unroll
    for (int im = 0; im < 4; im++) {
        #pragma unroll
        for (int j = 0; j < 4; j++) {
            const int col = warp_n + j * 8 + (lane & 3) * 2;   // 0..63
            #pragma unroll
            for (int half = 0; half < 2; half++) {
                const int m = warp_m + im * 16 + (lane >> 2) + half * 8;
                float v0 = acc[im][j][half * 2 + 0];
                float v1 = acc[im][j][half * 2 + 1];
                __nv_bfloat16 h0, l0, h1, l1;
                split1(v0, h0, l0); split1(v1, h1, l1);
                __nv_bfloat162 th, tl;
                th.x = h0; th.y = h1; tl.x = l0; tl.y = l1;
                __nv_bfloat16* base = g_ohs + (size_t)(bi * NT + m) * KX + hh * 64 + col;
                *(__nv_bfloat162*)(base)        = th;
                *(__nv_bfloat162*)(base + 512)  = tl;
                *(__nv_bfloat162*)(base + 1024) = th;
            }
        }
    }
}

// ---------------------------------------------------------------------------
extern "C" void kernel_launch(void* const* d_in, const int* in_sizes, int n_in,
                              void* d_out, int out_size)
{
    (void)in_sizes; (void)n_in; (void)out_size;
    const float* x      = (const float*)d_in[0];
    const float* qkv_w  = (const float*)d_in[1];
    const float* qkv_b  = (const float*)d_in[2];
    const float* pe_w   = (const float*)d_in[3];
    const float* pe_b   = (const float*)d_in[4];
    const float* rpb    = (const float*)d_in[5];
    const float* proj_w = (const float*)d_in[6];
    const float* proj_b = (const float*)d_in[7];
    float* out = (float*)d_out;

    static bool attr_done = false;
    if (!attr_done) {
        cudaFuncSetAttribute(gemm_mma<0>, cudaFuncAttributeMaxDynamicSharedMemorySize, GSMEM);
        cudaFuncSetAttribute(gemm_mma<1>, cudaFuncAttributeMaxDynamicSharedMemorySize, GSMEM);
        cudaFuncSetAttribute(s_mma, cudaFuncAttributeMaxDynamicSharedMemorySize, GSMEM);
        cudaFuncSetAttribute(av_mma, cudaFuncAttributeMaxDynamicSharedMemorySize, AVSMEM);
        attr_done = true;
    }

    __nv_bfloat16 *xs, *qws, *pws, *ohs;
    cudaGetSymbolAddress((void**)&xs,  g_xs);
    cudaGetSymbolAddress((void**)&qws, g_qws);
    cudaGetSymbolAddress((void**)&pws, g_pws);
    cudaGetSymbolAddress((void**)&ohs, g_ohs);

    split_a_kernel<<<(MTOT * MODEL / 2 + 255) / 256, 256>>>(x, xs, MTOT * MODEL / 2);
    split_b_kernel<<<(QKVN * MODEL / 2 + 255) / 256, 256>>>(qkv_w, qws, QKVN * MODEL / 2);
    split_b_kernel<<<(MODEL * MODEL / 2 + 255) / 256, 256>>>(proj_w, pws, MODEL * MODEL / 2);

    gemm_mma<0><<<dim3(QKVN / BN, MTOT / BM), 256, GSMEM>>>(xs, qws, qkv_b, nullptr);

    vt_kernel<<<NBH, 256>>>();
    s_mma<<<dim3(4, NBH), 256, GSMEM>>>();
    conv_softmax_kernel<<<dim3(16, NBH), 256>>>(pe_w, pe_b, rpb);
    av_mma<<<NBH, 256, AVSMEM>>>();

    gemm_mma<1><<<dim3(MODEL / BN, MTOT / BM), 256, GSMEM>>>(ohs, pws, proj_b, out);
}